// round 1
// baseline (speedup 1.0000x reference)
#include <cuda_runtime.h>

#define BM 128
#define BN 128
#define BK 16
#define TM 8
#define TN 8

// Problem constants: B=4, SQ=SKV=2048, D=1024
// Scratch (no allocations allowed -> __device__ globals)
__device__ float g_Q[8192u * 1024u];
__device__ float g_K[8192u * 1024u];
__device__ float g_V[8192u * 1024u];
__device__ float g_S[4u * 2048u * 2048u];

// C[m,n] = alpha * sum_k A[m,k] * (TRANS_B ? B[n,k] : B[k,n]) (+ bias[n])
// Batched via blockIdx.z with explicit strides.
template <bool TRANS_B, bool HAS_BIAS>
__global__ __launch_bounds__(256)
void sgemm_kernel(const float* __restrict__ Ag, const float* __restrict__ Bg,
                  const float* __restrict__ bias, float* __restrict__ Cg,
                  int M, int N, int K,
                  long long sA, long long sB, long long sC, float alpha)
{
    const float* A = Ag + (long long)blockIdx.z * sA;
    const float* B = Bg + (long long)blockIdx.z * sB;
    float*       C = Cg + (long long)blockIdx.z * sC;

    __shared__ float As[BK][BM];
    __shared__ float Bs[BK][BN];

    const int tid = threadIdx.x;       // 0..255
    const int tx  = tid & 15;          // 0..15
    const int ty  = tid >> 4;          // 0..15

    const int rowBase = blockIdx.y * BM;
    const int colBase = blockIdx.x * BN;

    // A-tile load mapping: 128 rows x 16 k, one float4 per thread per half
    const int aRow = tid >> 2;          // 0..63
    const int aCol = (tid & 3) * 4;     // 0,4,8,12
    // B-tile (NN) load mapping: 16 k-rows x 128 n
    const int bRow = tid >> 5;          // 0..7
    const int bCol = (tid & 31) * 4;    // 0..124

    float acc[TM][TN];
#pragma unroll
    for (int i = 0; i < TM; i++)
#pragma unroll
        for (int j = 0; j < TN; j++) acc[i][j] = 0.0f;

    for (int k0 = 0; k0 < K; k0 += BK) {
        // ---- stage A (transposed into As[k][m]) ----
#pragma unroll
        for (int r = 0; r < 2; r++) {
            const int row = aRow + r * 64;
            const float4 v = *reinterpret_cast<const float4*>(
                &A[(long long)(rowBase + row) * K + k0 + aCol]);
            As[aCol + 0][row] = v.x;
            As[aCol + 1][row] = v.y;
            As[aCol + 2][row] = v.z;
            As[aCol + 3][row] = v.w;
        }
        // ---- stage B ----
        if (TRANS_B) {
            // B is [N, K] row-major; stage transposed into Bs[k][n]
#pragma unroll
            for (int r = 0; r < 2; r++) {
                const int nrow = aRow + r * 64;
                const float4 v = *reinterpret_cast<const float4*>(
                    &B[(long long)(colBase + nrow) * K + k0 + aCol]);
                Bs[aCol + 0][nrow] = v.x;
                Bs[aCol + 1][nrow] = v.y;
                Bs[aCol + 2][nrow] = v.z;
                Bs[aCol + 3][nrow] = v.w;
            }
        } else {
            // B is [K, N] row-major; direct float4 copy
#pragma unroll
            for (int r = 0; r < 2; r++) {
                const int kk = bRow + r * 8;
                *reinterpret_cast<float4*>(&Bs[kk][bCol]) =
                    *reinterpret_cast<const float4*>(
                        &B[(long long)(k0 + kk) * N + colBase + bCol]);
            }
        }
        __syncthreads();

        // ---- compute 8x8 per thread ----
#pragma unroll
        for (int kk = 0; kk < BK; kk++) {
            float a[TM], b[TN];
            const float4 a0 = *reinterpret_cast<const float4*>(&As[kk][ty * TM]);
            const float4 a1 = *reinterpret_cast<const float4*>(&As[kk][ty * TM + 4]);
            a[0] = a0.x; a[1] = a0.y; a[2] = a0.z; a[3] = a0.w;
            a[4] = a1.x; a[5] = a1.y; a[6] = a1.z; a[7] = a1.w;
            const float4 b0 = *reinterpret_cast<const float4*>(&Bs[kk][tx * TN]);
            const float4 b1 = *reinterpret_cast<const float4*>(&Bs[kk][tx * TN + 4]);
            b[0] = b0.x; b[1] = b0.y; b[2] = b0.z; b[3] = b0.w;
            b[4] = b1.x; b[5] = b1.y; b[6] = b1.z; b[7] = b1.w;
#pragma unroll
            for (int i = 0; i < TM; i++)
#pragma unroll
                for (int j = 0; j < TN; j++)
                    acc[i][j] += a[i] * b[j];
        }
        __syncthreads();
    }

    // ---- epilogue ----
#pragma unroll
    for (int i = 0; i < TM; i++) {
        const long long row = rowBase + ty * TM + i;
#pragma unroll
        for (int j = 0; j < TN; j += 4) {
            const int col = colBase + tx * TN + j;
            float4 v;
            v.x = alpha * acc[i][j + 0];
            v.y = alpha * acc[i][j + 1];
            v.z = alpha * acc[i][j + 2];
            v.w = alpha * acc[i][j + 3];
            if (HAS_BIAS) {
                v.x += bias[col + 0];
                v.y += bias[col + 1];
                v.z += bias[col + 2];
                v.w += bias[col + 3];
            }
            *reinterpret_cast<float4*>(&C[row * N + col]) = v;
        }
    }
}

// Row softmax in place: one block per row.
__global__ __launch_bounds__(256)
void softmax_kernel(float* __restrict__ S, int ncols)
{
    const long long row = blockIdx.x;
    float* p = S + row * (long long)ncols;
    const int tid = threadIdx.x;
    __shared__ float red[256];

    float m = -1e30f;
    for (int c = tid; c < ncols; c += 256) m = fmaxf(m, p[c]);
    red[tid] = m;
    __syncthreads();
    for (int s = 128; s > 0; s >>= 1) {
        if (tid < s) red[tid] = fmaxf(red[tid], red[tid + s]);
        __syncthreads();
    }
    m = red[0];
    __syncthreads();

    float sum = 0.0f;
    for (int c = tid; c < ncols; c += 256) {
        const float e = __expf(p[c] - m);
        p[c] = e;
        sum += e;
    }
    red[tid] = sum;
    __syncthreads();
    for (int s = 128; s > 0; s >>= 1) {
        if (tid < s) red[tid] += red[tid + s];
        __syncthreads();
    }
    const float inv = 1.0f / red[0];
    __syncthreads();

    for (int c = tid; c < ncols; c += 256) p[c] *= inv;
}

extern "C" void kernel_launch(void* const* d_in, const int* in_sizes, int n_in,
                              void* d_out, int out_size)
{
    (void)in_sizes; (void)n_in; (void)out_size;
    const float* x       = (const float*)d_in[0]; // [4,2048,1024]
    const float* context = (const float*)d_in[1]; // [4,2048,1024]
    const float* Wq      = (const float*)d_in[2]; // [1024,1024] (in,out)
    const float* bq      = (const float*)d_in[3];
    const float* Wk      = (const float*)d_in[4];
    const float* bk      = (const float*)d_in[5];
    const float* Wv      = (const float*)d_in[6];
    const float* bv      = (const float*)d_in[7];
    float* out = (float*)d_out;                   // [4,2048,1024]

    float *Q, *K_, *V, *S;
    cudaGetSymbolAddress((void**)&Q,  g_Q);
    cudaGetSymbolAddress((void**)&K_, g_K);
    cudaGetSymbolAddress((void**)&V,  g_V);
    cudaGetSymbolAddress((void**)&S,  g_S);

    const int Bn = 4, SQ = 2048, D = 1024;
    const int MFlat = Bn * SQ; // 8192
    const float scale = 0.03125f; // 1/sqrt(1024)

    // Projections: [8192,1024] = [8192,1024] x [1024,1024] + bias
    dim3 gProj(D / BN, MFlat / BM, 1);
    sgemm_kernel<false, true><<<gProj, 256>>>(x,       Wq, bq, Q,  MFlat, D, D, 0, 0, 0, 1.0f);
    sgemm_kernel<false, true><<<gProj, 256>>>(context, Wk, bk, K_, MFlat, D, D, 0, 0, 0, 1.0f);
    sgemm_kernel<false, true><<<gProj, 256>>>(context, Wv, bv, V,  MFlat, D, D, 0, 0, 0, 1.0f);

    // Scores: S[b] = scale * Q[b] @ K[b]^T  -> [2048, 2048] per batch
    dim3 gS(SQ / BN, SQ / BM, Bn);
    sgemm_kernel<true, false><<<gS, 256>>>(Q, K_, nullptr, S,
                                           SQ, SQ, D,
                                           (long long)SQ * D, (long long)SQ * D,
                                           (long long)SQ * SQ, scale);

    // Softmax over rows of S
    softmax_kernel<<<Bn * SQ, 256>>>(S, SQ);

    // Output: out[b] = P[b] @ V[b]  -> [2048, 1024] per batch
    dim3 gO(D / BN, SQ / BM, Bn);
    sgemm_kernel<false, false><<<gO, 256>>>(S, V, nullptr, out,
                                            SQ, D, SQ,
                                            (long long)SQ * SQ, (long long)SQ * D,
                                            (long long)SQ * D, 1.0f);
}

// round 6
// speedup vs baseline: 1.3250x; 1.3250x over previous
#include <cuda_runtime.h>
#include <cstdint>

// ---------------------------------------------------------------------------
// Cross-attention B=4, SQ=SKV=2048, D=1024, fp32 in/out.
// tf32 3x-split GEMMs via base-ISA mma.sync.m16n8k8 (tcgen05 PTX is rejected
// by this harness's .target sm_103 pipeline).
// ---------------------------------------------------------------------------

__device__ float g_Q [8192u * 1024u];
__device__ float g_K [8192u * 1024u];
__device__ float g_Vt[4u * 1024u * 2048u];   // V^T per batch: [D, SKV]
__device__ float g_S [4u * 2048u * 2048u];
__device__ float g_Wt[3u * 1024u * 1024u];   // Wq^T, Wk^T, Wv^T  [out, in]

#define BM 128
#define BN 256
#define BK 16
#define STAGES 3
// padded row stride: 16 data floats + 4 pad -> bank pattern (20r+c)%32 distinct
#define RS 20
#define A_STAGE_FLOATS (BM * RS)          // 2560
#define B_STAGE_FLOATS (BN * RS)          // 5120
#define STAGE_FLOATS   (A_STAGE_FLOATS + B_STAGE_FLOATS)
#define SMEM_BYTES     (STAGES * STAGE_FLOATS * 4)   // 92160

__device__ __forceinline__ uint32_t smem_u32(const void* p) {
    uint32_t a;
    asm("{ .reg .u64 t; cvta.to.shared.u64 t, %1; cvt.u32.u64 %0, t; }" : "=r"(a) : "l"(p));
    return a;
}
__device__ __forceinline__ void cp16(uint32_t s, const void* g) {
    asm volatile("cp.async.cg.shared.global [%0], [%1], 16;" :: "r"(s), "l"(g) : "memory");
}
__device__ __forceinline__ void cp_commit() {
    asm volatile("cp.async.commit_group;" ::: "memory");
}
__device__ __forceinline__ void cp_wait1() {
    asm volatile("cp.async.wait_group 1;" ::: "memory");
}
__device__ __forceinline__ void tf32_split(float v, uint32_t& h, uint32_t& l) {
    asm("cvt.rna.tf32.f32 %0, %1;" : "=r"(h) : "f"(v));
    float lf = v - __uint_as_float(h);
    asm("cvt.rna.tf32.f32 %0, %1;" : "=r"(l) : "f"(lf));
}
__device__ __forceinline__ void mma8(float* d, const uint32_t* a, uint32_t b0, uint32_t b1) {
    asm volatile(
        "mma.sync.aligned.m16n8k8.row.col.f32.tf32.tf32.f32 "
        "{%0,%1,%2,%3}, {%4,%5,%6,%7}, {%8,%9}, {%0,%1,%2,%3};"
        : "+f"(d[0]), "+f"(d[1]), "+f"(d[2]), "+f"(d[3])
        : "r"(a[0]), "r"(a[1]), "r"(a[2]), "r"(a[3]), "r"(b0), "r"(b1));
}

// ---------------------------------------------------------------------------
// C[m,n] = alpha * sum_k A[m,k] * B[n,k] (+ bias[n]);  A:[M,K] B:[N,K] row-major.
// TRANS_C: write C[n*ldcT + m]. Batched via blockIdx.z.
// Requires M%128==0, N%256==0, K%16==0.
// ---------------------------------------------------------------------------
template <bool HAS_BIAS, bool TRANS_C>
__global__ __launch_bounds__(256, 1)
void tf32_gemm(const float* __restrict__ Ag, const float* __restrict__ Bg,
               const float* __restrict__ bias, float* __restrict__ Cg,
               int M, int N, int K,
               long long sA, long long sB, long long sC,
               float alpha, int ldcT)
{
    extern __shared__ float smemf[];
    const uint32_t sbase = smem_u32(smemf);

    const int tid  = threadIdx.x;
    const int wid  = tid >> 5;
    const int lane = tid & 31;
    const int r    = lane >> 2;      // group id
    const int cq   = lane & 3;       // thread-in-group

    const int mBase = (wid >> 2) * 64;   // warp M offset in CTA tile
    const int nBase = (wid & 3) * 64;    // warp N offset

    const int rowBase = blockIdx.y * BM;
    const int colBase = blockIdx.x * BN;

    const float* A = Ag + (long long)blockIdx.z * sA + (long long)rowBase * K;
    const float* B = Bg + (long long)blockIdx.z * sB + (long long)colBase * K;
    float*       C = Cg + (long long)blockIdx.z * sC;

    const int nC = K / BK;

    // ---- async stage issue ----
    auto issue = [&](int cIdx) {
        const int k0 = cIdx * BK;
        const int s  = cIdx % STAGES;
        const uint32_t sAb = sbase + (uint32_t)(s * STAGE_FLOATS) * 4u;
        const uint32_t sBb = sAb + A_STAGE_FLOATS * 4u;
#pragma unroll
        for (int i = 0; i < 2; i++) {              // A: 512 chunks of 16B
            const int idx = tid + i * 256;
            const int row = idx >> 2, cc = idx & 3;
            cp16(sAb + (uint32_t)(row * RS + cc * 4) * 4u,
                 A + (long long)row * K + k0 + cc * 4);
        }
#pragma unroll
        for (int i = 0; i < 4; i++) {              // B: 1024 chunks
            const int idx = tid + i * 256;
            const int row = idx >> 2, cc = idx & 3;
            cp16(sBb + (uint32_t)(row * RS + cc * 4) * 4u,
                 B + (long long)row * K + k0 + cc * 4);
        }
        cp_commit();
    };

    float acc[4][8][4];
#pragma unroll
    for (int mi = 0; mi < 4; mi++)
#pragma unroll
        for (int nj = 0; nj < 8; nj++)
#pragma unroll
            for (int q = 0; q < 4; q++) acc[mi][nj][q] = 0.0f;

    issue(0);
    issue(1);

    for (int c = 0; c < nC; c++) {
        cp_wait1();
        __syncthreads();
        if (c + 2 < nC) issue(c + 2); else cp_commit();

        const float* As = smemf + (c % STAGES) * STAGE_FLOATS;
        const float* Bs = As + A_STAGE_FLOATS;

#pragma unroll
        for (int ks = 0; ks < 2; ks++) {
            const int kk = ks * 8;
            uint32_t ah[4][4], al[4][4];
#pragma unroll
            for (int mi = 0; mi < 4; mi++) {
                const float* ap = As + (mBase + mi * 16 + r) * RS + kk + cq;
                tf32_split(ap[0],          ah[mi][0], al[mi][0]);
                tf32_split(ap[8 * RS],     ah[mi][1], al[mi][1]);
                tf32_split(ap[4],          ah[mi][2], al[mi][2]);
                tf32_split(ap[8 * RS + 4], ah[mi][3], al[mi][3]);
            }
#pragma unroll
            for (int nj = 0; nj < 8; nj++) {
                const float* bp = Bs + (nBase + nj * 8 + r) * RS + kk + cq;
                uint32_t bh0, bl0, bh1, bl1;
                tf32_split(bp[0], bh0, bl0);
                tf32_split(bp[4], bh1, bl1);
#pragma unroll
                for (int mi = 0; mi < 4; mi++) {
                    mma8(acc[mi][nj], ah[mi], bh0, bh1);
                    mma8(acc[mi][nj], ah[mi], bl0, bl1);
                    mma8(acc[mi][nj], al[mi], bh0, bh1);
                }
            }
        }
    }
    __syncthreads();

    // ---- epilogue ----
#pragma unroll
    for (int nj = 0; nj < 8; nj++) {
        const int n0 = colBase + nBase + nj * 8 + 2 * cq;
        float2 bv = make_float2(0.f, 0.f);
        if (HAS_BIAS) bv = *reinterpret_cast<const float2*>(&bias[n0]);
#pragma unroll
        for (int mi = 0; mi < 4; mi++) {
            const int m0 = rowBase + mBase + mi * 16 + r;
            const float* d = acc[mi][nj];
            if (TRANS_C) {
                C[(long long)(n0 + 0) * ldcT + m0]     = d[0] * alpha + bv.x;
                C[(long long)(n0 + 1) * ldcT + m0]     = d[1] * alpha + bv.y;
                C[(long long)(n0 + 0) * ldcT + m0 + 8] = d[2] * alpha + bv.x;
                C[(long long)(n0 + 1) * ldcT + m0 + 8] = d[3] * alpha + bv.y;
            } else {
                float2 v0 = make_float2(d[0] * alpha + bv.x, d[1] * alpha + bv.y);
                float2 v1 = make_float2(d[2] * alpha + bv.x, d[3] * alpha + bv.y);
                *reinterpret_cast<float2*>(&C[(long long)m0 * N + n0])       = v0;
                *reinterpret_cast<float2*>(&C[(long long)(m0 + 8) * N + n0]) = v1;
            }
        }
    }
}

// ---------------- transpose 1024x1024 ----------------
__global__ __launch_bounds__(256)
void transpose1024(const float* __restrict__ in, float* __restrict__ out)
{
    __shared__ float t[32][33];
    const int bx = blockIdx.x * 32, by = blockIdx.y * 32;
    const int txl = threadIdx.x, tyl = threadIdx.y;
#pragma unroll
    for (int rr = tyl; rr < 32; rr += 8)
        t[rr][txl] = in[(long long)(by + rr) * 1024 + bx + txl];
    __syncthreads();
#pragma unroll
    for (int rr = tyl; rr < 32; rr += 8)
        out[(long long)(bx + rr) * 1024 + by + txl] = t[txl][rr];
}

// ---------------- softmax: one 2048-col row per block, register-resident ----
__global__ __launch_bounds__(256)
void softmax_kernel(float* __restrict__ S)
{
    float* p = S + (long long)blockIdx.x * 2048;
    const int tid  = threadIdx.x;
    const int wid  = tid >> 5;
    const int lane = tid & 31;
    __shared__ float red[8];

    float4 v0 = reinterpret_cast<float4*>(p)[tid];
    float4 v1 = reinterpret_cast<float4*>(p)[tid + 256];

    float m = fmaxf(fmaxf(fmaxf(v0.x, v0.y), fmaxf(v0.z, v0.w)),
                    fmaxf(fmaxf(v1.x, v1.y), fmaxf(v1.z, v1.w)));
#pragma unroll
    for (int o = 16; o; o >>= 1) m = fmaxf(m, __shfl_xor_sync(~0u, m, o));
    if (lane == 0) red[wid] = m;
    __syncthreads();
    m = fmaxf(fmaxf(fmaxf(red[0], red[1]), fmaxf(red[2], red[3])),
              fmaxf(fmaxf(red[4], red[5]), fmaxf(red[6], red[7])));
    __syncthreads();

    v0.x = __expf(v0.x - m); v0.y = __expf(v0.y - m);
    v0.z = __expf(v0.z - m); v0.w = __expf(v0.w - m);
    v1.x = __expf(v1.x - m); v1.y = __expf(v1.y - m);
    v1.z = __expf(v1.z - m); v1.w = __expf(v1.w - m);

    float s = (v0.x + v0.y) + (v0.z + v0.w) + (v1.x + v1.y) + (v1.z + v1.w);
#pragma unroll
    for (int o = 16; o; o >>= 1) s += __shfl_xor_sync(~0u, s, o);
    if (lane == 0) red[wid] = s;
    __syncthreads();
    s = (red[0] + red[1]) + (red[2] + red[3]) + (red[4] + red[5]) + (red[6] + red[7]);
    const float inv = 1.0f / s;

    v0.x *= inv; v0.y *= inv; v0.z *= inv; v0.w *= inv;
    v1.x *= inv; v1.y *= inv; v1.z *= inv; v1.w *= inv;
    reinterpret_cast<float4*>(p)[tid]       = v0;
    reinterpret_cast<float4*>(p)[tid + 256] = v1;
}

// ---------------------------------------------------------------------------
extern "C" void kernel_launch(void* const* d_in, const int* in_sizes, int n_in,
                              void* d_out, int out_size)
{
    (void)in_sizes; (void)n_in; (void)out_size;
    const float* x       = (const float*)d_in[0];
    const float* context = (const float*)d_in[1];
    const float* Wq      = (const float*)d_in[2];
    const float* bq      = (const float*)d_in[3];
    const float* Wk      = (const float*)d_in[4];
    const float* bk      = (const float*)d_in[5];
    const float* Wv      = (const float*)d_in[6];
    const float* bv      = (const float*)d_in[7];
    float* out = (float*)d_out;

    float *Q, *Kp, *Vt, *S, *Wt;
    cudaGetSymbolAddress((void**)&Q,  g_Q);
    cudaGetSymbolAddress((void**)&Kp, g_K);
    cudaGetSymbolAddress((void**)&Vt, g_Vt);
    cudaGetSymbolAddress((void**)&S,  g_S);
    cudaGetSymbolAddress((void**)&Wt, g_Wt);
    float* Wtq = Wt;
    float* Wtk = Wt + 1024u * 1024u;
    float* Wtv = Wt + 2u * 1024u * 1024u;

    cudaFuncSetAttribute(tf32_gemm<true,  false>, cudaFuncAttributeMaxDynamicSharedMemorySize, SMEM_BYTES);
    cudaFuncSetAttribute(tf32_gemm<true,  true >, cudaFuncAttributeMaxDynamicSharedMemorySize, SMEM_BYTES);
    cudaFuncSetAttribute(tf32_gemm<false, false>, cudaFuncAttributeMaxDynamicSharedMemorySize, SMEM_BYTES);

    const float scale = 0.03125f;  // 1/sqrt(1024)

    dim3 tg(32, 32);
    transpose1024<<<tg, dim3(32, 8)>>>(Wq, Wtq);
    transpose1024<<<tg, dim3(32, 8)>>>(Wk, Wtk);
    transpose1024<<<tg, dim3(32, 8)>>>(Wv, Wtv);

    // Q = x Wq + bq ; K = ctx Wk + bk (flat M=8192, N=1024, K=1024)
    dim3 gP(1024 / BN, 8192 / BM, 1);
    tf32_gemm<true, false><<<gP, 256, SMEM_BYTES>>>(x,       Wtq, bq, Q,  8192, 1024, 1024, 0, 0, 0, 1.0f, 0);
    tf32_gemm<true, false><<<gP, 256, SMEM_BYTES>>>(context, Wtk, bk, Kp, 8192, 1024, 1024, 0, 0, 0, 1.0f, 0);

    // V^T per batch (epilogue transposes): M=2048, N=1024, K=1024
    dim3 gV(1024 / BN, 2048 / BM, 4);
    tf32_gemm<true, true><<<gV, 256, SMEM_BYTES>>>(context, Wtv, bv, Vt, 2048, 1024, 1024,
                                                   2048LL * 1024, 0, 1024LL * 2048, 1.0f, 2048);

    // S = scale * Q K^T per batch: M=2048, N=2048, K=1024
    dim3 gS(2048 / BN, 2048 / BM, 4);
    tf32_gemm<false, false><<<gS, 256, SMEM_BYTES>>>(Q, Kp, nullptr, S, 2048, 2048, 1024,
                                                     2048LL * 1024, 2048LL * 1024, 2048LL * 2048, scale, 0);

    softmax_kernel<<<4 * 2048, 256>>>(S);

    // out = P V per batch: M=2048, N=1024, K=2048 (B = V^T, K-major)
    dim3 gO(1024 / BN, 2048 / BM, 4);
    tf32_gemm<false, false><<<gO, 256, SMEM_BYTES>>>(S, Vt, nullptr, out, 2048, 1024, 2048,
                                                     2048LL * 2048, 1024LL * 2048, 2048LL * 1024, 1.0f, 0);
}

// round 8
// speedup vs baseline: 2.0999x; 1.5849x over previous
#include <cuda_runtime.h>
#include <cuda_fp16.h>
#include <cstdint>

// ---------------------------------------------------------------------------
// Cross-attention B=4, SQ=SKV=2048, D=1024, fp32 in/out.
// All GEMMs: fp16 3x-split (hi/lo planes pre-split in global memory),
// mma.sync.m16n8k16.f32.f16.f16.f32, ldmatrix fragment loads,
// cp.async 3-stage pipeline. CTA tile 128x256, warp tile 64x64.
// ---------------------------------------------------------------------------

// fp16 hi/lo planes (pre-split operands)
__device__ __half g_xh [8192u * 1024u], g_xl [8192u * 1024u];
__device__ __half g_ch [8192u * 1024u], g_cl [8192u * 1024u];
__device__ __half g_Wth[3u * 1024u * 1024u], g_Wtl[3u * 1024u * 1024u];
__device__ __half g_Qh [8192u * 1024u], g_Ql [8192u * 1024u];
__device__ __half g_Kh [8192u * 1024u], g_Kl [8192u * 1024u];
__device__ __half g_Vth[4u * 1024u * 2048u], g_Vtl[4u * 1024u * 2048u];
__device__ __half g_Ph [4u * 2048u * 2048u], g_Pl [4u * 2048u * 2048u];
__device__ float  g_S  [4u * 2048u * 2048u];

#define BM 128
#define BN 256
#define RSH 24                 // smem row stride in halves (48B) -> conflict-free ldmatrix
#define A_LO_OFF 6144          // 128*48
#define B_HI_OFF 12288
#define B_LO_OFF 24576         // +256*48
#define STAGE_BYTES 36864
#define NSTAGE 3
#define SMEM_BYTES (NSTAGE * STAGE_BYTES)   // 110592

__device__ __forceinline__ uint32_t smem_u32(const void* p) {
    uint32_t a;
    asm("{ .reg .u64 t; cvta.to.shared.u64 t, %1; cvt.u32.u64 %0, t; }" : "=r"(a) : "l"(p));
    return a;
}
__device__ __forceinline__ void cp16(uint32_t s, const void* g) {
    asm volatile("cp.async.cg.shared.global [%0], [%1], 16;" :: "r"(s), "l"(g) : "memory");
}
__device__ __forceinline__ void cp_commit() { asm volatile("cp.async.commit_group;" ::: "memory"); }
__device__ __forceinline__ void cp_wait1()  { asm volatile("cp.async.wait_group 1;" ::: "memory"); }

__device__ __forceinline__ void ldm4(uint32_t* r, uint32_t addr) {
    asm volatile("ldmatrix.sync.aligned.m8n8.x4.shared.b16 {%0,%1,%2,%3}, [%4];"
        : "=r"(r[0]), "=r"(r[1]), "=r"(r[2]), "=r"(r[3]) : "r"(addr));
}
__device__ __forceinline__ void mma16(float* d, const uint32_t* a, uint32_t b0, uint32_t b1) {
    asm volatile(
        "mma.sync.aligned.m16n8k16.row.col.f32.f16.f16.f32 "
        "{%0,%1,%2,%3}, {%4,%5,%6,%7}, {%8,%9}, {%0,%1,%2,%3};"
        : "+f"(d[0]), "+f"(d[1]), "+f"(d[2]), "+f"(d[3])
        : "r"(a[0]), "r"(a[1]), "r"(a[2]), "r"(a[3]), "r"(b0), "r"(b1));
}
__device__ __forceinline__ void splitf(float v, __half& h, __half& l) {
    h = __float2half_rn(v);
    l = __float2half_rn(v - __half2float(h));
}

// ---------------------------------------------------------------------------
// C[m,n] = alpha * sum_k A[m,k]*B[n,k] (+bias[n])
// A planes [M,K], B planes [N,K], K-contiguous. Batched via blockIdx.z.
// SPLIT_OUT: write hi/lo half planes (Ch,Cl); else fp32 Cf.
// TRANS_C: write C[n*ldcT + m].
// ---------------------------------------------------------------------------
template <bool SPLIT_OUT, bool TRANS_C, bool HAS_BIAS>
__global__ __launch_bounds__(256, 1)
void gemm16(const __half* __restrict__ Agh, const __half* __restrict__ Agl,
            const __half* __restrict__ Bgh, const __half* __restrict__ Bgl,
            const float* __restrict__ bias,
            float* __restrict__ Cfg, __half* __restrict__ Chg, __half* __restrict__ Clg,
            int M, int N, int K,
            long long sA, long long sB, long long sC,
            float alpha, int ldcT)
{
    extern __shared__ char smem[];
    const uint32_t sbase = smem_u32(smem);

    const int tid  = threadIdx.x;
    const int wid  = tid >> 5;
    const int lane = tid & 31;
    const int r    = lane >> 2;
    const int cq   = lane & 3;

    const int mBase = (wid >> 2) * 64;
    const int nBase = (wid & 3) * 64;

    const int rowBase = blockIdx.y * BM;
    const int colBase = blockIdx.x * BN;

    const __half* Ah = Agh + (long long)blockIdx.z * sA + (long long)rowBase * K;
    const __half* Al = Agl + (long long)blockIdx.z * sA + (long long)rowBase * K;
    const __half* Bh = Bgh + (long long)blockIdx.z * sB + (long long)colBase * K;
    const __half* Bl = Bgl + (long long)blockIdx.z * sB + (long long)colBase * K;

    const int nC = K >> 4;

    // cp.async stage issue: 1536 x 16B chunks, 6 per thread
    auto issue = [&](int cIdx) {
        const long long k0 = (long long)cIdx << 4;
        const uint32_t st = sbase + (uint32_t)((cIdx % NSTAGE) * STAGE_BYTES);
#pragma unroll
        for (int i = 0; i < 6; i++) {
            const int g = tid + i * 256;
            if (g < 512) {                       // A planes (i = 0,1)
                const int plane = g >> 8;
                const int h = g & 255;
                const int row = h >> 1, cc = h & 1;
                const __half* src = (plane ? Al : Ah) + (long long)row * K + k0 + cc * 8;
                cp16(st + (plane ? A_LO_OFF : 0) + row * 48 + cc * 16, src);
            } else {                             // B planes (i = 2..5)
                const int h2 = g - 512;
                const int plane = h2 >> 9;
                const int h = h2 & 511;
                const int row = h >> 1, cc = h & 1;
                const __half* src = (plane ? Bl : Bh) + (long long)row * K + k0 + cc * 8;
                cp16(st + (plane ? B_LO_OFF : B_HI_OFF) + row * 48 + cc * 16, src);
            }
        }
        cp_commit();
    };

    // ldmatrix per-lane byte offsets within a plane
    const uint32_t aOffB = (uint32_t)(((mBase + (lane & 7) + ((lane & 8) ? 8 : 0)) * RSH
                                       + ((lane & 16) ? 8 : 0)) * 2);
    const uint32_t bOffB = (uint32_t)(((nBase + (lane & 7) + ((lane & 16) ? 8 : 0)) * RSH
                                       + ((lane & 8) ? 8 : 0)) * 2);

    float acc[4][8][4];
#pragma unroll
    for (int mi = 0; mi < 4; mi++)
#pragma unroll
        for (int nj = 0; nj < 8; nj++)
#pragma unroll
            for (int q = 0; q < 4; q++) acc[mi][nj][q] = 0.0f;

    issue(0);
    issue(1);

    for (int c = 0; c < nC; c++) {
        cp_wait1();
        __syncthreads();
        if (c + 2 < nC) issue(c + 2); else cp_commit();

        const uint32_t st = sbase + (uint32_t)((c % NSTAGE) * STAGE_BYTES);

        uint32_t ah[4][4], al2[4][4], bh[4][4], bl2[4][4];
#pragma unroll
        for (int mi = 0; mi < 4; mi++) {
            ldm4(ah[mi],  st + aOffB + mi * 768);             // 16 rows * 48B
            ldm4(al2[mi], st + A_LO_OFF + aOffB + mi * 768);
        }
#pragma unroll
        for (int p = 0; p < 4; p++) {
            ldm4(bh[p],  st + B_HI_OFF + bOffB + p * 768);
            ldm4(bl2[p], st + B_LO_OFF + bOffB + p * 768);
        }

        // pass 1: Ah * Bh
#pragma unroll
        for (int nj = 0; nj < 8; nj++) {
            const uint32_t b0 = bh[nj >> 1][(nj & 1) * 2];
            const uint32_t b1 = bh[nj >> 1][(nj & 1) * 2 + 1];
#pragma unroll
            for (int mi = 0; mi < 4; mi++) mma16(acc[mi][nj], ah[mi], b0, b1);
        }
        // pass 2: Ah * Bl
#pragma unroll
        for (int nj = 0; nj < 8; nj++) {
            const uint32_t b0 = bl2[nj >> 1][(nj & 1) * 2];
            const uint32_t b1 = bl2[nj >> 1][(nj & 1) * 2 + 1];
#pragma unroll
            for (int mi = 0; mi < 4; mi++) mma16(acc[mi][nj], ah[mi], b0, b1);
        }
        // pass 3: Al * Bh
#pragma unroll
        for (int nj = 0; nj < 8; nj++) {
            const uint32_t b0 = bh[nj >> 1][(nj & 1) * 2];
            const uint32_t b1 = bh[nj >> 1][(nj & 1) * 2 + 1];
#pragma unroll
            for (int mi = 0; mi < 4; mi++) mma16(acc[mi][nj], al2[mi], b0, b1);
        }
    }
    __syncthreads();

    // ---- epilogue ----
    float* Cf  = SPLIT_OUT ? nullptr : (Cfg + (long long)blockIdx.z * sC);
    __half* Ch = SPLIT_OUT ? (Chg + (long long)blockIdx.z * sC) : nullptr;
    __half* Cl = SPLIT_OUT ? (Clg + (long long)blockIdx.z * sC) : nullptr;

#pragma unroll
    for (int nj = 0; nj < 8; nj++) {
        const int n0 = colBase + nBase + nj * 8 + 2 * cq;
        float bx = 0.f, by = 0.f;
        if (HAS_BIAS) { float2 bv = *reinterpret_cast<const float2*>(&bias[n0]); bx = bv.x; by = bv.y; }
#pragma unroll
        for (int mi = 0; mi < 4; mi++) {
            const int m0 = rowBase + mBase + mi * 16 + r;
            const float* d = acc[mi][nj];
            const float v0 = d[0] * alpha + bx, v1 = d[1] * alpha + by;
            const float v2 = d[2] * alpha + bx, v3 = d[3] * alpha + by;
            if (SPLIT_OUT) {
                __half h0, h1, h2, h3, l0, l1, l2, l3;
                splitf(v0, h0, l0); splitf(v1, h1, l1);
                splitf(v2, h2, l2); splitf(v3, h3, l3);
                if (TRANS_C) {
                    Ch[(long long)(n0 + 0) * ldcT + m0]     = h0;
                    Ch[(long long)(n0 + 1) * ldcT + m0]     = h1;
                    Ch[(long long)(n0 + 0) * ldcT + m0 + 8] = h2;
                    Ch[(long long)(n0 + 1) * ldcT + m0 + 8] = h3;
                    Cl[(long long)(n0 + 0) * ldcT + m0]     = l0;
                    Cl[(long long)(n0 + 1) * ldcT + m0]     = l1;
                    Cl[(long long)(n0 + 0) * ldcT + m0 + 8] = l2;
                    Cl[(long long)(n0 + 1) * ldcT + m0 + 8] = l3;
                } else {
                    *reinterpret_cast<__half2*>(&Ch[(long long)m0 * N + n0])       = __halves2half2(h0, h1);
                    *reinterpret_cast<__half2*>(&Ch[(long long)(m0 + 8) * N + n0]) = __halves2half2(h2, h3);
                    *reinterpret_cast<__half2*>(&Cl[(long long)m0 * N + n0])       = __halves2half2(l0, l1);
                    *reinterpret_cast<__half2*>(&Cl[(long long)(m0 + 8) * N + n0]) = __halves2half2(l2, l3);
                }
            } else {
                *reinterpret_cast<float2*>(&Cf[(long long)m0 * N + n0])       = make_float2(v0, v1);
                *reinterpret_cast<float2*>(&Cf[(long long)(m0 + 8) * N + n0]) = make_float2(v2, v3);
            }
        }
    }
}

// ---------------- elementwise split: fp32 -> hi/lo half planes ----------------
__global__ __launch_bounds__(256)
void split_mat(const float* __restrict__ src, __half* __restrict__ h, __half* __restrict__ l)
{
    const int i = blockIdx.x * 256 + threadIdx.x;
    const float4 v = reinterpret_cast<const float4*>(src)[i];
    __half h0, h1, h2, h3, l0, l1, l2, l3;
    splitf(v.x, h0, l0); splitf(v.y, h1, l1); splitf(v.z, h2, l2); splitf(v.w, h3, l3);
    reinterpret_cast<__half2*>(h)[i * 2 + 0] = __halves2half2(h0, h1);
    reinterpret_cast<__half2*>(h)[i * 2 + 1] = __halves2half2(h2, h3);
    reinterpret_cast<__half2*>(l)[i * 2 + 0] = __halves2half2(l0, l1);
    reinterpret_cast<__half2*>(l)[i * 2 + 1] = __halves2half2(l2, l3);
}

// ---------------- transpose 1024x1024 + split ----------------
__global__ __launch_bounds__(256)
void transpose_split(const float* __restrict__ in, __half* __restrict__ th, __half* __restrict__ tl)
{
    __shared__ float t[32][33];
    const int bx = blockIdx.x * 32, by = blockIdx.y * 32;
    const int txl = threadIdx.x, tyl = threadIdx.y;
#pragma unroll
    for (int rr = tyl; rr < 32; rr += 8)
        t[rr][txl] = in[(long long)(by + rr) * 1024 + bx + txl];
    __syncthreads();
#pragma unroll
    for (int rr = tyl; rr < 32; rr += 8) {
        __half h, l;
        splitf(t[txl][rr], h, l);
        th[(long long)(bx + rr) * 1024 + by + txl] = h;
        tl[(long long)(bx + rr) * 1024 + by + txl] = l;
    }
}

// ---------------- softmax: fp32 S row -> P hi/lo planes ----------------
__global__ __launch_bounds__(256)
void softmax_split(const float* __restrict__ S, __half* __restrict__ Ph, __half* __restrict__ Pl)
{
    const float* p = S + (long long)blockIdx.x * 2048;
    const int tid  = threadIdx.x;
    const int wid  = tid >> 5;
    const int lane = tid & 31;
    __shared__ float red[8];

    float4 v0 = reinterpret_cast<const float4*>(p)[tid];
    float4 v1 = reinterpret_cast<const float4*>(p)[tid + 256];

    float m = fmaxf(fmaxf(fmaxf(v0.x, v0.y), fmaxf(v0.z, v0.w)),
                    fmaxf(fmaxf(v1.x, v1.y), fmaxf(v1.z, v1.w)));
#pragma unroll
    for (int o = 16; o; o >>= 1) m = fmaxf(m, __shfl_xor_sync(~0u, m, o));
    if (lane == 0) red[wid] = m;
    __syncthreads();
    m = fmaxf(fmaxf(fmaxf(red[0], red[1]), fmaxf(red[2], red[3])),
              fmaxf(fmaxf(red[4], red[5]), fmaxf(red[6], red[7])));
    __syncthreads();

    v0.x = __expf(v0.x - m); v0.y = __expf(v0.y - m);
    v0.z = __expf(v0.z - m); v0.w = __expf(v0.w - m);
    v1.x = __expf(v1.x - m); v1.y = __expf(v1.y - m);
    v1.z = __expf(v1.z - m); v1.w = __expf(v1.w - m);

    float s = (v0.x + v0.y) + (v0.z + v0.w) + (v1.x + v1.y) + (v1.z + v1.w);
#pragma unroll
    for (int o = 16; o; o >>= 1) s += __shfl_xor_sync(~0u, s, o);
    if (lane == 0) red[wid] = s;
    __syncthreads();
    s = (red[0] + red[1]) + (red[2] + red[3]) + (red[4] + red[5]) + (red[6] + red[7]);
    const float inv = 1.0f / s;

    v0.x *= inv; v0.y *= inv; v0.z *= inv; v0.w *= inv;
    v1.x *= inv; v1.y *= inv; v1.z *= inv; v1.w *= inv;

    __half2* PH = reinterpret_cast<__half2*>(Ph + (long long)blockIdx.x * 2048);
    __half2* PL = reinterpret_cast<__half2*>(Pl + (long long)blockIdx.x * 2048);
    __half h0, h1, h2, h3, l0, l1, l2, l3;
    splitf(v0.x, h0, l0); splitf(v0.y, h1, l1); splitf(v0.z, h2, l2); splitf(v0.w, h3, l3);
    PH[tid * 2 + 0] = __halves2half2(h0, h1); PH[tid * 2 + 1] = __halves2half2(h2, h3);
    PL[tid * 2 + 0] = __halves2half2(l0, l1); PL[tid * 2 + 1] = __halves2half2(l2, l3);
    splitf(v1.x, h0, l0); splitf(v1.y, h1, l1); splitf(v1.z, h2, l2); splitf(v1.w, h3, l3);
    PH[512 + tid * 2 + 0] = __halves2half2(h0, h1); PH[512 + tid * 2 + 1] = __halves2half2(h2, h3);
    PL[512 + tid * 2 + 0] = __halves2half2(l0, l1); PL[512 + tid * 2 + 1] = __halves2half2(l2, l3);
}

// ---------------------------------------------------------------------------
extern "C" void kernel_launch(void* const* d_in, const int* in_sizes, int n_in,
                              void* d_out, int out_size)
{
    (void)in_sizes; (void)n_in; (void)out_size;
    const float* x       = (const float*)d_in[0];
    const float* context = (const float*)d_in[1];
    const float* Wq      = (const float*)d_in[2];
    const float* bq      = (const float*)d_in[3];
    const float* Wk      = (const float*)d_in[4];
    const float* bk      = (const float*)d_in[5];
    const float* Wv      = (const float*)d_in[6];
    const float* bv      = (const float*)d_in[7];
    float* out = (float*)d_out;

    __half *xh, *xl, *ch, *cl, *Wth, *Wtl, *Qh, *Ql, *Kh, *Kl, *Vth, *Vtl, *Ph, *Pl;
    float* S;
    cudaGetSymbolAddress((void**)&xh,  g_xh);  cudaGetSymbolAddress((void**)&xl,  g_xl);
    cudaGetSymbolAddress((void**)&ch,  g_ch);  cudaGetSymbolAddress((void**)&cl,  g_cl);
    cudaGetSymbolAddress((void**)&Wth, g_Wth); cudaGetSymbolAddress((void**)&Wtl, g_Wtl);
    cudaGetSymbolAddress((void**)&Qh,  g_Qh);  cudaGetSymbolAddress((void**)&Ql,  g_Ql);
    cudaGetSymbolAddress((void**)&Kh,  g_Kh);  cudaGetSymbolAddress((void**)&Kl,  g_Kl);
    cudaGetSymbolAddress((void**)&Vth, g_Vth); cudaGetSymbolAddress((void**)&Vtl, g_Vtl);
    cudaGetSymbolAddress((void**)&Ph,  g_Ph);  cudaGetSymbolAddress((void**)&Pl,  g_Pl);
    cudaGetSymbolAddress((void**)&S,   g_S);

    cudaFuncSetAttribute(gemm16<true,  false, true >, cudaFuncAttributeMaxDynamicSharedMemorySize, SMEM_BYTES);
    cudaFuncSetAttribute(gemm16<true,  true,  true >, cudaFuncAttributeMaxDynamicSharedMemorySize, SMEM_BYTES);
    cudaFuncSetAttribute(gemm16<false, false, false>, cudaFuncAttributeMaxDynamicSharedMemorySize, SMEM_BYTES);

    const float scale = 0.03125f;  // 1/sqrt(1024)

    // ---- prep: split inputs / transpose+split weights ----
    split_mat<<<8192, 256>>>(x,       xh, xl);
    split_mat<<<8192, 256>>>(context, ch, cl);
    dim3 tg(32, 32);
    transpose_split<<<tg, dim3(32, 8)>>>(Wq, Wth,                 Wtl);
    transpose_split<<<tg, dim3(32, 8)>>>(Wk, Wth + 1024u * 1024u, Wtl + 1024u * 1024u);
    transpose_split<<<tg, dim3(32, 8)>>>(Wv, Wth + 2u * 1024u * 1024u, Wtl + 2u * 1024u * 1024u);

    // ---- projections ----
    dim3 gP(1024 / BN, 8192 / BM, 1);
    gemm16<true, false, true><<<gP, 256, SMEM_BYTES>>>(
        xh, xl, Wth, Wtl, bq, nullptr, Qh, Ql, 8192, 1024, 1024, 0, 0, 0, 1.0f, 0);
    gemm16<true, false, true><<<gP, 256, SMEM_BYTES>>>(
        ch, cl, Wth + 1024u * 1024u, Wtl + 1024u * 1024u, bk, nullptr, Kh, Kl,
        8192, 1024, 1024, 0, 0, 0, 1.0f, 0);

    // V^T per batch (epilogue transposes into [D, SKV] planes)
    dim3 gV(1024 / BN, 2048 / BM, 4);
    gemm16<true, true, true><<<gV, 256, SMEM_BYTES>>>(
        ch, cl, Wth + 2u * 1024u * 1024u, Wtl + 2u * 1024u * 1024u, bv, nullptr, Vth, Vtl,
        2048, 1024, 1024, 2048LL * 1024, 0, 1024LL * 2048, 1.0f, 2048);

    // ---- S = scale * Q K^T per batch ----
    dim3 gS(2048 / BN, 2048 / BM, 4);
    gemm16<false, false, false><<<gS, 256, SMEM_BYTES>>>(
        Qh, Ql, Kh, Kl, nullptr, S, nullptr, nullptr,
        2048, 2048, 1024, 2048LL * 1024, 2048LL * 1024, 2048LL * 2048, scale, 0);

    // ---- softmax -> P planes ----
    softmax_split<<<4 * 2048, 256>>>(S, Ph, Pl);

    // ---- out = P V per batch ----
    dim3 gO(1024 / BN, 2048 / BM, 4);
    gemm16<false, false, false><<<gO, 256, SMEM_BYTES>>>(
        Ph, Pl, Vth, Vtl, nullptr, out, nullptr, nullptr,
        2048, 1024, 2048, 2048LL * 2048, 1024LL * 2048, 2048LL * 1024, 1.0f, 0);
}

// round 9
// speedup vs baseline: 5.4361x; 2.5888x over previous
#include <cuda_runtime.h>
#include <cuda_fp16.h>
#include <cstdint>

// ---------------------------------------------------------------------------
// Cross-attention B=4, SQ=SKV=2048, D=1024, fp32 in/out.
// Single-pass fp16 HMMA (fp32 accumulate) everywhere; error budget ~3e-4 < 1e-3.
// CTA tile 128x256, warp 64x64, BK=32, 4-stage cp.async pipeline.
// ---------------------------------------------------------------------------

__device__ __half g_xh [8192u * 1024u];
__device__ __half g_ch [8192u * 1024u];
__device__ __half g_Wt [3u * 1024u * 1024u];    // Wq^T, Wk^T, Wv^T (fp16)
__device__ __half g_Qh [8192u * 1024u];
__device__ __half g_Kh [8192u * 1024u];
__device__ __half g_Vt [4u * 1024u * 2048u];    // V^T per batch [D, SKV]
__device__ __half g_Ph [4u * 2048u * 2048u];
__device__ float  g_S  [4u * 2048u * 2048u];

#define BM 128
#define BN 256
#define BK 32
#define RSB 80                  // smem row stride in BYTES (32 halves + 16B pad)
#define A_BYTES (128 * RSB)     // 10240
#define B_OFF   A_BYTES
#define STAGE_BYTES (A_BYTES + 256 * RSB)   // 30720
#define NSTAGE 4
#define SMEM_BYTES (NSTAGE * STAGE_BYTES)   // 122880

__device__ __forceinline__ uint32_t smem_u32(const void* p) {
    uint32_t a;
    asm("{ .reg .u64 t; cvta.to.shared.u64 t, %1; cvt.u32.u64 %0, t; }" : "=r"(a) : "l"(p));
    return a;
}
__device__ __forceinline__ void cp16(uint32_t s, const void* g) {
    asm volatile("cp.async.cg.shared.global [%0], [%1], 16;" :: "r"(s), "l"(g) : "memory");
}
__device__ __forceinline__ void cp_commit() { asm volatile("cp.async.commit_group;" ::: "memory"); }
__device__ __forceinline__ void cp_wait2()  { asm volatile("cp.async.wait_group 2;" ::: "memory"); }

__device__ __forceinline__ void ldm4(uint32_t* r, uint32_t addr) {
    asm volatile("ldmatrix.sync.aligned.m8n8.x4.shared.b16 {%0,%1,%2,%3}, [%4];"
        : "=r"(r[0]), "=r"(r[1]), "=r"(r[2]), "=r"(r[3]) : "r"(addr));
}
__device__ __forceinline__ void mma16(float* d, const uint32_t* a, uint32_t b0, uint32_t b1) {
    asm volatile(
        "mma.sync.aligned.m16n8k16.row.col.f32.f16.f16.f32 "
        "{%0,%1,%2,%3}, {%4,%5,%6,%7}, {%8,%9}, {%0,%1,%2,%3};"
        : "+f"(d[0]), "+f"(d[1]), "+f"(d[2]), "+f"(d[3])
        : "r"(a[0]), "r"(a[1]), "r"(a[2]), "r"(a[3]), "r"(b0), "r"(b1));
}

// ---------------------------------------------------------------------------
// MODE 0: batched fp32 out:  C = alpha * A[M,K] x B[N,K]^T, strides sA/sB/sC.
// MODE 1: fused projections: z=0: Qh = xh Wq + bq
//                            z=1: Kh = ch Wk + bk
//                            z=2: Vt = (ch Wv + bv)^T per batch (half out)
// ---------------------------------------------------------------------------
template <int MODE>
__global__ __launch_bounds__(256, 1)
void gemm_f16(const __half* __restrict__ A0, const __half* __restrict__ A1,
              const __half* __restrict__ Bg,
              const float* __restrict__ b0p, const float* __restrict__ b1p,
              const float* __restrict__ b2p,
              float* __restrict__ Cf,
              __half* __restrict__ O0, __half* __restrict__ O1, __half* __restrict__ O2,
              int M, int N, int K,
              long long sA, long long sB, long long sC, float alpha)
{
    extern __shared__ char smem[];
    const uint32_t sbase = smem_u32(smem);

    const int tid  = threadIdx.x;
    const int wid  = tid >> 5;
    const int lane = tid & 31;
    const int r    = lane >> 2;
    const int cq   = lane & 3;
    const int z    = blockIdx.z;

    const int mBase = (wid >> 2) * 64;
    const int nBase = (wid & 3) * 64;
    const int rowBase = blockIdx.y * BM;
    const int colBase = blockIdx.x * BN;

    const __half* A;
    const __half* B;
    const float*  bias = nullptr;
    if (MODE == 1) {
        A    = (z == 0) ? A0 : A1;
        B    = Bg + (uint32_t)z * (1u << 20);
        bias = (z == 0) ? b0p : (z == 1) ? b1p : b2p;
    } else {
        A = A0 + (long long)z * sA;
        B = Bg + (long long)z * sB;
    }
    A += (long long)rowBase * K;
    B += (long long)colBase * K;

    const int nC = K / BK;

    auto issue = [&](int cIdx) {
        const long long k0 = (long long)cIdx * BK;
        const uint32_t st = sbase + (uint32_t)((cIdx % NSTAGE) * STAGE_BYTES);
#pragma unroll
        for (int i = 0; i < 6; i++) {
            const int g = tid + i * 256;
            if (g < 512) {                              // A: 128 rows x 4 chunks
                const int row = g >> 2, cc = g & 3;
                cp16(st + row * RSB + cc * 16, A + (long long)row * K + k0 + cc * 8);
            } else {                                    // B: 256 rows x 4 chunks
                const int h = g - 512;
                const int row = h >> 2, cc = h & 3;
                cp16(st + B_OFF + row * RSB + cc * 16, B + (long long)row * K + k0 + cc * 8);
            }
        }
        cp_commit();
    };

    const uint32_t aOffB = (uint32_t)((mBase + (lane & 15)) * RSB + ((lane & 16) ? 16 : 0));
    const uint32_t bOffB = (uint32_t)((nBase + (lane & 7) + ((lane & 16) ? 8 : 0)) * RSB
                                      + ((lane & 8) ? 16 : 0));

    float acc[4][8][4];
#pragma unroll
    for (int mi = 0; mi < 4; mi++)
#pragma unroll
        for (int nj = 0; nj < 8; nj++)
#pragma unroll
            for (int q = 0; q < 4; q++) acc[mi][nj][q] = 0.0f;

    issue(0); issue(1); issue(2);

    for (int c = 0; c < nC; c++) {
        cp_wait2();
        __syncthreads();
        if (c + 3 < nC) issue(c + 3); else cp_commit();

        const uint32_t st = sbase + (uint32_t)((c % NSTAGE) * STAGE_BYTES);

#pragma unroll
        for (int sub = 0; sub < 2; sub++) {
            uint32_t ah[4][4], bh[4][4];
#pragma unroll
            for (int mi = 0; mi < 4; mi++)
                ldm4(ah[mi], st + aOffB + mi * (16 * RSB) + sub * 32);
#pragma unroll
            for (int p = 0; p < 4; p++)
                ldm4(bh[p], st + B_OFF + bOffB + p * (16 * RSB) + sub * 32);
#pragma unroll
            for (int nj = 0; nj < 8; nj++) {
                const uint32_t bb0 = bh[nj >> 1][(nj & 1) * 2];
                const uint32_t bb1 = bh[nj >> 1][(nj & 1) * 2 + 1];
#pragma unroll
                for (int mi = 0; mi < 4; mi++) mma16(acc[mi][nj], ah[mi], bb0, bb1);
            }
        }
    }
    __syncthreads();

    // ---- epilogue ----
    if (MODE == 0) {
        float* C = Cf + (long long)z * sC;
#pragma unroll
        for (int nj = 0; nj < 8; nj++) {
            const int n0 = colBase + nBase + nj * 8 + 2 * cq;
#pragma unroll
            for (int mi = 0; mi < 4; mi++) {
                const int m0 = rowBase + mBase + mi * 16 + r;
                const float* d = acc[mi][nj];
                *reinterpret_cast<float2*>(&C[(long long)m0 * N + n0]) =
                    make_float2(d[0] * alpha, d[1] * alpha);
                *reinterpret_cast<float2*>(&C[(long long)(m0 + 8) * N + n0]) =
                    make_float2(d[2] * alpha, d[3] * alpha);
            }
        }
    } else {
#pragma unroll
        for (int nj = 0; nj < 8; nj++) {
            const int n0 = colBase + nBase + nj * 8 + 2 * cq;
            const float2 bv = *reinterpret_cast<const float2*>(&bias[n0]);
#pragma unroll
            for (int mi = 0; mi < 4; mi++) {
                const int m0 = rowBase + mBase + mi * 16 + r;
                const float* d = acc[mi][nj];
                const float v0 = d[0] + bv.x, v1 = d[1] + bv.y;
                const float v2 = d[2] + bv.x, v3 = d[3] + bv.y;
                if (z < 2) {
                    __half* O = z ? O1 : O0;
                    *reinterpret_cast<__half2*>(&O[(long long)m0 * 1024 + n0]) =
                        __floats2half2_rn(v0, v1);
                    *reinterpret_cast<__half2*>(&O[(long long)(m0 + 8) * 1024 + n0]) =
                        __floats2half2_rn(v2, v3);
                } else {
                    // V^T: m0 = b*2048 + s, n0 = d  ->  O2[b][d][s]
                    const int bb = m0 >> 11, s = m0 & 2047;
                    __half* O = O2 + (long long)bb * (1024u * 2048u);
                    O[(long long)(n0 + 0) * 2048 + s]     = __float2half_rn(v0);
                    O[(long long)(n0 + 1) * 2048 + s]     = __float2half_rn(v1);
                    O[(long long)(n0 + 0) * 2048 + s + 8] = __float2half_rn(v2);
                    O[(long long)(n0 + 1) * 2048 + s + 8] = __float2half_rn(v3);
                }
            }
        }
    }
}

// ---------------- fp32 -> fp16 convert ----------------
__global__ __launch_bounds__(256)
void conv_half(const float* __restrict__ src, __half* __restrict__ dst)
{
    const int i = blockIdx.x * 256 + threadIdx.x;
    const float4 v = reinterpret_cast<const float4*>(src)[i];
    reinterpret_cast<__half2*>(dst)[i * 2 + 0] = __floats2half2_rn(v.x, v.y);
    reinterpret_cast<__half2*>(dst)[i * 2 + 1] = __floats2half2_rn(v.z, v.w);
}

// ---------------- transpose 1024x1024 -> fp16 ----------------
__global__ __launch_bounds__(256)
void transpose_conv(const float* __restrict__ in, __half* __restrict__ t)
{
    __shared__ float ts[32][33];
    const int bx = blockIdx.x * 32, by = blockIdx.y * 32;
    const int txl = threadIdx.x, tyl = threadIdx.y;
#pragma unroll
    for (int rr = tyl; rr < 32; rr += 8)
        ts[rr][txl] = in[(long long)(by + rr) * 1024 + bx + txl];
    __syncthreads();
#pragma unroll
    for (int rr = tyl; rr < 32; rr += 8)
        t[(long long)(bx + rr) * 1024 + by + txl] = __float2half_rn(ts[txl][rr]);
}

// ---------------- softmax: fp32 S row -> fp16 P row ----------------
__global__ __launch_bounds__(256)
void softmax_h(const float* __restrict__ S, __half* __restrict__ Ph)
{
    const float* p = S + (long long)blockIdx.x * 2048;
    const int tid  = threadIdx.x;
    const int wid  = tid >> 5;
    const int lane = tid & 31;
    __shared__ float red[8];

    float4 v0 = reinterpret_cast<const float4*>(p)[tid];
    float4 v1 = reinterpret_cast<const float4*>(p)[tid + 256];

    float m = fmaxf(fmaxf(fmaxf(v0.x, v0.y), fmaxf(v0.z, v0.w)),
                    fmaxf(fmaxf(v1.x, v1.y), fmaxf(v1.z, v1.w)));
#pragma unroll
    for (int o = 16; o; o >>= 1) m = fmaxf(m, __shfl_xor_sync(~0u, m, o));
    if (lane == 0) red[wid] = m;
    __syncthreads();
    m = fmaxf(fmaxf(fmaxf(red[0], red[1]), fmaxf(red[2], red[3])),
              fmaxf(fmaxf(red[4], red[5]), fmaxf(red[6], red[7])));
    __syncthreads();

    v0.x = __expf(v0.x - m); v0.y = __expf(v0.y - m);
    v0.z = __expf(v0.z - m); v0.w = __expf(v0.w - m);
    v1.x = __expf(v1.x - m); v1.y = __expf(v1.y - m);
    v1.z = __expf(v1.z - m); v1.w = __expf(v1.w - m);

    float s = (v0.x + v0.y) + (v0.z + v0.w) + (v1.x + v1.y) + (v1.z + v1.w);
#pragma unroll
    for (int o = 16; o; o >>= 1) s += __shfl_xor_sync(~0u, s, o);
    if (lane == 0) red[wid] = s;
    __syncthreads();
    s = (red[0] + red[1]) + (red[2] + red[3]) + (red[4] + red[5]) + (red[6] + red[7]);
    const float inv = 1.0f / s;

    __half2* PH = reinterpret_cast<__half2*>(Ph + (long long)blockIdx.x * 2048);
    PH[tid * 2 + 0]       = __floats2half2_rn(v0.x * inv, v0.y * inv);
    PH[tid * 2 + 1]       = __floats2half2_rn(v0.z * inv, v0.w * inv);
    PH[512 + tid * 2 + 0] = __floats2half2_rn(v1.x * inv, v1.y * inv);
    PH[512 + tid * 2 + 1] = __floats2half2_rn(v1.z * inv, v1.w * inv);
}

// ---------------------------------------------------------------------------
extern "C" void kernel_launch(void* const* d_in, const int* in_sizes, int n_in,
                              void* d_out, int out_size)
{
    (void)in_sizes; (void)n_in; (void)out_size;
    const float* x       = (const float*)d_in[0];
    const float* context = (const float*)d_in[1];
    const float* Wq      = (const float*)d_in[2];
    const float* bq      = (const float*)d_in[3];
    const float* Wk      = (const float*)d_in[4];
    const float* bk      = (const float*)d_in[5];
    const float* Wv      = (const float*)d_in[6];
    const float* bv      = (const float*)d_in[7];
    float* out = (float*)d_out;

    __half *xh, *ch, *Wt, *Qh, *Kh, *Vt, *Ph;
    float* S;
    cudaGetSymbolAddress((void**)&xh, g_xh);
    cudaGetSymbolAddress((void**)&ch, g_ch);
    cudaGetSymbolAddress((void**)&Wt, g_Wt);
    cudaGetSymbolAddress((void**)&Qh, g_Qh);
    cudaGetSymbolAddress((void**)&Kh, g_Kh);
    cudaGetSymbolAddress((void**)&Vt, g_Vt);
    cudaGetSymbolAddress((void**)&Ph, g_Ph);
    cudaGetSymbolAddress((void**)&S,  g_S);

    cudaFuncSetAttribute(gemm_f16<0>, cudaFuncAttributeMaxDynamicSharedMemorySize, SMEM_BYTES);
    cudaFuncSetAttribute(gemm_f16<1>, cudaFuncAttributeMaxDynamicSharedMemorySize, SMEM_BYTES);

    const float scale = 0.03125f;  // 1/sqrt(1024)

    // prep
    conv_half<<<8192, 256>>>(x,       xh);
    conv_half<<<8192, 256>>>(context, ch);
    dim3 tg(32, 32);
    transpose_conv<<<tg, dim3(32, 8)>>>(Wq, Wt);
    transpose_conv<<<tg, dim3(32, 8)>>>(Wk, Wt + (1u << 20));
    transpose_conv<<<tg, dim3(32, 8)>>>(Wv, Wt + (2u << 20));

    // fused projections: grid.z = {Q, K, V^T}
    gemm_f16<1><<<dim3(4, 64, 3), 256, SMEM_BYTES>>>(
        xh, ch, Wt, bq, bk, bv, nullptr, Qh, Kh, Vt,
        8192, 1024, 1024, 0, 0, 0, 1.0f);

    // S = scale * Q K^T per batch
    gemm_f16<0><<<dim3(8, 16, 4), 256, SMEM_BYTES>>>(
        Qh, nullptr, Kh, nullptr, nullptr, nullptr, S, nullptr, nullptr, nullptr,
        2048, 2048, 1024, 2048LL * 1024, 2048LL * 1024, 2048LL * 2048, scale);

    softmax_h<<<4 * 2048, 256>>>(S, Ph);

    // out = P V per batch (B = V^T, K-contiguous over SKV)
    gemm_f16<0><<<dim3(4, 16, 4), 256, SMEM_BYTES>>>(
        Ph, nullptr, Vt, nullptr, nullptr, nullptr, out, nullptr, nullptr, nullptr,
        2048, 1024, 2048, 2048LL * 2048, 1024LL * 2048, 2048LL * 1024, 1.0f);
}

// round 10
// speedup vs baseline: 6.9184x; 1.2727x over previous
#include <cuda_runtime.h>
#include <cuda_fp16.h>
#include <cstdint>

// ---------------------------------------------------------------------------
// Cross-attention B=4, SQ=SKV=2048, D=1024, fp32 in/out.
// Single-pass fp16 HMMA (fp32 accumulate). CTA 128x128 (128 thr, 4 warps,
// warp tile 64x64), BK=32, 3-stage cp.async, 2 CTAs/SM for barrier overlap.
// ---------------------------------------------------------------------------

__device__ __half g_xh [8192u * 1024u];
__device__ __half g_ch [8192u * 1024u];
__device__ __half g_Wt [3u * 1024u * 1024u];    // Wq^T, Wk^T, Wv^T (fp16)
__device__ __half g_Qh [8192u * 1024u];
__device__ __half g_Kh [8192u * 1024u];
__device__ __half g_Vt [4u * 1024u * 2048u];    // V^T per batch [D, SKV]
__device__ __half g_Ph [4u * 2048u * 2048u];
__device__ float  g_S  [4u * 2048u * 2048u];

#define BM 128
#define BN 128
#define BK 32
#define RSB 80                  // smem row stride in BYTES (64B data + 16B pad)
#define A_BYTES (128 * RSB)     // 10240
#define B_OFF   A_BYTES
#define STAGE_BYTES (2 * A_BYTES)           // 20480
#define NSTAGE 3
#define SMEM_BYTES (NSTAGE * STAGE_BYTES)   // 61440

__device__ __forceinline__ uint32_t smem_u32(const void* p) {
    uint32_t a;
    asm("{ .reg .u64 t; cvta.to.shared.u64 t, %1; cvt.u32.u64 %0, t; }" : "=r"(a) : "l"(p));
    return a;
}
__device__ __forceinline__ void cp16(uint32_t s, const void* g) {
    asm volatile("cp.async.cg.shared.global [%0], [%1], 16;" :: "r"(s), "l"(g) : "memory");
}
__device__ __forceinline__ void cp_commit() { asm volatile("cp.async.commit_group;" ::: "memory"); }
__device__ __forceinline__ void cp_wait1()  { asm volatile("cp.async.wait_group 1;" ::: "memory"); }

__device__ __forceinline__ void ldm4(uint32_t* r, uint32_t addr) {
    asm volatile("ldmatrix.sync.aligned.m8n8.x4.shared.b16 {%0,%1,%2,%3}, [%4];"
        : "=r"(r[0]), "=r"(r[1]), "=r"(r[2]), "=r"(r[3]) : "r"(addr));
}
__device__ __forceinline__ void mma16(float* d, const uint32_t* a, uint32_t b0, uint32_t b1) {
    asm volatile(
        "mma.sync.aligned.m16n8k16.row.col.f32.f16.f16.f32 "
        "{%0,%1,%2,%3}, {%4,%5,%6,%7}, {%8,%9}, {%0,%1,%2,%3};"
        : "+f"(d[0]), "+f"(d[1]), "+f"(d[2]), "+f"(d[3])
        : "r"(a[0]), "r"(a[1]), "r"(a[2]), "r"(a[3]), "r"(b0), "r"(b1));
}

// ---------------------------------------------------------------------------
// MODE 0: batched fp32 out:  C = alpha * A[M,K] x B[N,K]^T, strides sA/sB/sC.
// MODE 1: fused projections: z=0: Qh = xh Wq + bq
//                            z=1: Kh = ch Wk + bk
//                            z=2: Vt = (ch Wv + bv)^T per batch (half out)
// ---------------------------------------------------------------------------
template <int MODE>
__global__ __launch_bounds__(128, 2)
void gemm_f16(const __half* __restrict__ A0, const __half* __restrict__ A1,
              const __half* __restrict__ Bg,
              const float* __restrict__ b0p, const float* __restrict__ b1p,
              const float* __restrict__ b2p,
              float* __restrict__ Cf,
              __half* __restrict__ O0, __half* __restrict__ O1, __half* __restrict__ O2,
              int M, int N, int K,
              long long sA, long long sB, long long sC, float alpha)
{
    extern __shared__ char smem[];
    const uint32_t sbase = smem_u32(smem);

    const int tid  = threadIdx.x;       // 0..127
    const int wid  = tid >> 5;          // 0..3
    const int lane = tid & 31;
    const int r    = lane >> 2;
    const int cq   = lane & 3;
    const int z    = blockIdx.z;

    const int mBase = (wid >> 1) * 64;
    const int nBase = (wid & 1) * 64;
    const int rowBase = blockIdx.y * BM;
    const int colBase = blockIdx.x * BN;

    const __half* A;
    const __half* B;
    const float*  bias = nullptr;
    if (MODE == 1) {
        A    = (z == 0) ? A0 : A1;
        B    = Bg + (uint32_t)z * (1u << 20);
        bias = (z == 0) ? b0p : (z == 1) ? b1p : b2p;
    } else {
        A = A0 + (long long)z * sA;
        B = Bg + (long long)z * sB;
    }
    A += (long long)rowBase * K;
    B += (long long)colBase * K;

    const int nC = K / BK;

    // 1024 cp16 per stage (A 512 + B 512), 128 threads -> 8 each
    auto issue = [&](int cIdx) {
        const long long k0 = (long long)cIdx * BK;
        const uint32_t st = sbase + (uint32_t)((cIdx % NSTAGE) * STAGE_BYTES);
#pragma unroll
        for (int i = 0; i < 8; i++) {
            const int g = tid + i * 128;
            if (g < 512) {                              // A: 128 rows x 4 chunks
                const int row = g >> 2, cc = g & 3;
                cp16(st + row * RSB + cc * 16, A + (long long)row * K + k0 + cc * 8);
            } else {                                    // B: 128 rows x 4 chunks
                const int h = g - 512;
                const int row = h >> 2, cc = h & 3;
                cp16(st + B_OFF + row * RSB + cc * 16, B + (long long)row * K + k0 + cc * 8);
            }
        }
        cp_commit();
    };

    const uint32_t aOffB = (uint32_t)((mBase + (lane & 15)) * RSB + ((lane & 16) ? 16 : 0));
    const uint32_t bOffB = (uint32_t)((nBase + (lane & 7) + ((lane & 16) ? 8 : 0)) * RSB
                                      + ((lane & 8) ? 16 : 0));

    float acc[4][8][4];
#pragma unroll
    for (int mi = 0; mi < 4; mi++)
#pragma unroll
        for (int nj = 0; nj < 8; nj++)
#pragma unroll
            for (int q = 0; q < 4; q++) acc[mi][nj][q] = 0.0f;

    issue(0); issue(1);

    for (int c = 0; c < nC; c++) {
        cp_wait1();
        __syncthreads();
        if (c + 2 < nC) issue(c + 2); else cp_commit();

        const uint32_t st = sbase + (uint32_t)((c % NSTAGE) * STAGE_BYTES);

#pragma unroll
        for (int sub = 0; sub < 2; sub++) {
            uint32_t ah[4][4], bh[4][4];
#pragma unroll
            for (int mi = 0; mi < 4; mi++)
                ldm4(ah[mi], st + aOffB + mi * (16 * RSB) + sub * 32);
#pragma unroll
            for (int p = 0; p < 4; p++)
                ldm4(bh[p], st + B_OFF + bOffB + p * (16 * RSB) + sub * 32);
#pragma unroll
            for (int nj = 0; nj < 8; nj++) {
                const uint32_t bb0 = bh[nj >> 1][(nj & 1) * 2];
                const uint32_t bb1 = bh[nj >> 1][(nj & 1) * 2 + 1];
#pragma unroll
                for (int mi = 0; mi < 4; mi++) mma16(acc[mi][nj], ah[mi], bb0, bb1);
            }
        }
    }
    __syncthreads();

    // ---- epilogue ----
    if (MODE == 0) {
        float* C = Cf + (long long)z * sC;
#pragma unroll
        for (int nj = 0; nj < 8; nj++) {
            const int n0 = colBase + nBase + nj * 8 + 2 * cq;
#pragma unroll
            for (int mi = 0; mi < 4; mi++) {
                const int m0 = rowBase + mBase + mi * 16 + r;
                const float* d = acc[mi][nj];
                *reinterpret_cast<float2*>(&C[(long long)m0 * N + n0]) =
                    make_float2(d[0] * alpha, d[1] * alpha);
                *reinterpret_cast<float2*>(&C[(long long)(m0 + 8) * N + n0]) =
                    make_float2(d[2] * alpha, d[3] * alpha);
            }
        }
    } else {
#pragma unroll
        for (int nj = 0; nj < 8; nj++) {
            const int n0 = colBase + nBase + nj * 8 + 2 * cq;
            const float2 bv = *reinterpret_cast<const float2*>(&bias[n0]);
#pragma unroll
            for (int mi = 0; mi < 4; mi++) {
                const int m0 = rowBase + mBase + mi * 16 + r;
                const float* d = acc[mi][nj];
                const float v0 = d[0] + bv.x, v1 = d[1] + bv.y;
                const float v2 = d[2] + bv.x, v3 = d[3] + bv.y;
                if (z < 2) {
                    __half* O = z ? O1 : O0;
                    *reinterpret_cast<__half2*>(&O[(long long)m0 * 1024 + n0]) =
                        __floats2half2_rn(v0, v1);
                    *reinterpret_cast<__half2*>(&O[(long long)(m0 + 8) * 1024 + n0]) =
                        __floats2half2_rn(v2, v3);
                } else {
                    // V^T: m0 = b*2048 + s, n0 = d  ->  O2[b][d][s]
                    const int bb = m0 >> 11, s = m0 & 2047;
                    __half* O = O2 + (long long)bb * (1024u * 2048u);
                    O[(long long)(n0 + 0) * 2048 + s]     = __float2half_rn(v0);
                    O[(long long)(n0 + 1) * 2048 + s]     = __float2half_rn(v1);
                    O[(long long)(n0 + 0) * 2048 + s + 8] = __float2half_rn(v2);
                    O[(long long)(n0 + 1) * 2048 + s + 8] = __float2half_rn(v3);
                }
            }
        }
    }
}

// ---------------- fp32 -> fp16 convert (x and context fused) ----------------
__global__ __launch_bounds__(256)
void conv_half2(const float* __restrict__ s0, __half* __restrict__ d0,
                const float* __restrict__ s1, __half* __restrict__ d1)
{
    const bool second = blockIdx.x >= 8192;
    const float* src = second ? s1 : s0;
    __half* dst      = second ? d1 : d0;
    const int i = (second ? blockIdx.x - 8192 : blockIdx.x) * 256 + threadIdx.x;
    const float4 v = reinterpret_cast<const float4*>(src)[i];
    reinterpret_cast<__half2*>(dst)[i * 2 + 0] = __floats2half2_rn(v.x, v.y);
    reinterpret_cast<__half2*>(dst)[i * 2 + 1] = __floats2half2_rn(v.z, v.w);
}

// ---------------- transpose 1024x1024 -> fp16, z = weight index ----------------
__global__ __launch_bounds__(256)
void transpose_conv3(const float* __restrict__ w0, const float* __restrict__ w1,
                     const float* __restrict__ w2, __half* __restrict__ t)
{
    __shared__ float ts[32][33];
    const int z = blockIdx.z;
    const float* in = (z == 0) ? w0 : (z == 1) ? w1 : w2;
    __half* tz = t + ((uint32_t)z << 20);
    const int bx = blockIdx.x * 32, by = blockIdx.y * 32;
    const int txl = threadIdx.x, tyl = threadIdx.y;
#pragma unroll
    for (int rr = tyl; rr < 32; rr += 8)
        ts[rr][txl] = in[(long long)(by + rr) * 1024 + bx + txl];
    __syncthreads();
#pragma unroll
    for (int rr = tyl; rr < 32; rr += 8)
        tz[(long long)(bx + rr) * 1024 + by + txl] = __float2half_rn(ts[txl][rr]);
}

// ---------------- softmax: fp32 S row -> fp16 P row ----------------
__global__ __launch_bounds__(256)
void softmax_h(const float* __restrict__ S, __half* __restrict__ Ph)
{
    const float* p = S + (long long)blockIdx.x * 2048;
    const int tid  = threadIdx.x;
    const int wid  = tid >> 5;
    const int lane = tid & 31;
    __shared__ float red[8];

    float4 v0 = reinterpret_cast<const float4*>(p)[tid];
    float4 v1 = reinterpret_cast<const float4*>(p)[tid + 256];

    float m = fmaxf(fmaxf(fmaxf(v0.x, v0.y), fmaxf(v0.z, v0.w)),
                    fmaxf(fmaxf(v1.x, v1.y), fmaxf(v1.z, v1.w)));
#pragma unroll
    for (int o = 16; o; o >>= 1) m = fmaxf(m, __shfl_xor_sync(~0u, m, o));
    if (lane == 0) red[wid] = m;
    __syncthreads();
    m = fmaxf(fmaxf(fmaxf(red[0], red[1]), fmaxf(red[2], red[3])),
              fmaxf(fmaxf(red[4], red[5]), fmaxf(red[6], red[7])));
    __syncthreads();

    v0.x = __expf(v0.x - m); v0.y = __expf(v0.y - m);
    v0.z = __expf(v0.z - m); v0.w = __expf(v0.w - m);
    v1.x = __expf(v1.x - m); v1.y = __expf(v1.y - m);
    v1.z = __expf(v1.z - m); v1.w = __expf(v1.w - m);

    float s = (v0.x + v0.y) + (v0.z + v0.w) + (v1.x + v1.y) + (v1.z + v1.w);
#pragma unroll
    for (int o = 16; o; o >>= 1) s += __shfl_xor_sync(~0u, s, o);
    if (lane == 0) red[wid] = s;
    __syncthreads();
    s = (red[0] + red[1]) + (red[2] + red[3]) + (red[4] + red[5]) + (red[6] + red[7]);
    const float inv = 1.0f / s;

    __half2* PH = reinterpret_cast<__half2*>(Ph + (long long)blockIdx.x * 2048);
    PH[tid * 2 + 0]       = __floats2half2_rn(v0.x * inv, v0.y * inv);
    PH[tid * 2 + 1]       = __floats2half2_rn(v0.z * inv, v0.w * inv);
    PH[512 + tid * 2 + 0] = __floats2half2_rn(v1.x * inv, v1.y * inv);
    PH[512 + tid * 2 + 1] = __floats2half2_rn(v1.z * inv, v1.w * inv);
}

// ---------------------------------------------------------------------------
extern "C" void kernel_launch(void* const* d_in, const int* in_sizes, int n_in,
                              void* d_out, int out_size)
{
    (void)in_sizes; (void)n_in; (void)out_size;
    const float* x       = (const float*)d_in[0];
    const float* context = (const float*)d_in[1];
    const float* Wq      = (const float*)d_in[2];
    const float* bq      = (const float*)d_in[3];
    const float* Wk      = (const float*)d_in[4];
    const float* bk      = (const float*)d_in[5];
    const float* Wv      = (const float*)d_in[6];
    const float* bv      = (const float*)d_in[7];
    float* out = (float*)d_out;

    __half *xh, *ch, *Wt, *Qh, *Kh, *Vt, *Ph;
    float* S;
    cudaGetSymbolAddress((void**)&xh, g_xh);
    cudaGetSymbolAddress((void**)&ch, g_ch);
    cudaGetSymbolAddress((void**)&Wt, g_Wt);
    cudaGetSymbolAddress((void**)&Qh, g_Qh);
    cudaGetSymbolAddress((void**)&Kh, g_Kh);
    cudaGetSymbolAddress((void**)&Vt, g_Vt);
    cudaGetSymbolAddress((void**)&Ph, g_Ph);
    cudaGetSymbolAddress((void**)&S,  g_S);

    cudaFuncSetAttribute(gemm_f16<0>, cudaFuncAttributeMaxDynamicSharedMemorySize, SMEM_BYTES);
    cudaFuncSetAttribute(gemm_f16<1>, cudaFuncAttributeMaxDynamicSharedMemorySize, SMEM_BYTES);

    const float scale = 0.03125f;  // 1/sqrt(1024)

    // prep
    conv_half2<<<16384, 256>>>(x, xh, context, ch);
    transpose_conv3<<<dim3(32, 32, 3), dim3(32, 8)>>>(Wq, Wk, Wv, Wt);

    // fused projections: grid.z = {Q, K, V^T}
    gemm_f16<1><<<dim3(8, 64, 3), 128, SMEM_BYTES>>>(
        xh, ch, Wt, bq, bk, bv, nullptr, Qh, Kh, Vt,
        8192, 1024, 1024, 0, 0, 0, 1.0f);

    // S = scale * Q K^T per batch
    gemm_f16<0><<<dim3(16, 16, 4), 128, SMEM_BYTES>>>(
        Qh, nullptr, Kh, nullptr, nullptr, nullptr, S, nullptr, nullptr, nullptr,
        2048, 2048, 1024, 2048LL * 1024, 2048LL * 1024, 2048LL * 2048, scale);

    softmax_h<<<4 * 2048, 256>>>(S, Ph);

    // out = P V per batch (B = V^T, K-contiguous over SKV)
    gemm_f16<0><<<dim3(8, 16, 4), 128, SMEM_BYTES>>>(
        Ph, nullptr, Vt, nullptr, nullptr, nullptr, out, nullptr, nullptr, nullptr,
        2048, 1024, 2048, 2048LL * 2048, 1024LL * 2048, 2048LL * 1024, 1.0f);
}

// round 11
// speedup vs baseline: 7.0095x; 1.0132x over previous
#include <cuda_runtime.h>
#include <cuda_fp16.h>
#include <cstdint>

// ---------------------------------------------------------------------------
// Cross-attention B=4, SQ=SKV=2048, D=1024, fp32 in/out.
// Single-pass fp16 HMMA (fp32 accumulate). CTA 128x128 (128 thr, 4 warps,
// warp tile 64x64), BK=64, 3-stage cp.async, 2 CTAs/SM, register
// double-buffered ldmatrix fragments.
// ---------------------------------------------------------------------------

__device__ __half g_xh [8192u * 1024u];
__device__ __half g_ch [8192u * 1024u];
__device__ __half g_Wt [3u * 1024u * 1024u];    // Wq^T, Wk^T, Wv^T (fp16)
__device__ __half g_Qh [8192u * 1024u];
__device__ __half g_Kh [8192u * 1024u];
__device__ __half g_Vt [4u * 1024u * 2048u];    // V^T per batch [D, SKV]
__device__ __half g_Ph [4u * 2048u * 2048u];
__device__ float  g_S  [4u * 2048u * 2048u];

#define BM 128
#define BN 128
#define BK 64
#define RSB 144                 // smem row stride bytes (128B data + 16B pad)
#define A_BYTES (128 * RSB)     // 18432
#define B_OFF   A_BYTES
#define STAGE_BYTES (2 * A_BYTES)           // 36864
#define NSTAGE 3
#define SMEM_BYTES (NSTAGE * STAGE_BYTES)   // 110592

__device__ __forceinline__ uint32_t smem_u32(const void* p) {
    uint32_t a;
    asm("{ .reg .u64 t; cvta.to.shared.u64 t, %1; cvt.u32.u64 %0, t; }" : "=r"(a) : "l"(p));
    return a;
}
__device__ __forceinline__ void cp16(uint32_t s, const void* g) {
    asm volatile("cp.async.cg.shared.global [%0], [%1], 16;" :: "r"(s), "l"(g) : "memory");
}
__device__ __forceinline__ void cp_commit() { asm volatile("cp.async.commit_group;" ::: "memory"); }
__device__ __forceinline__ void cp_wait1()  { asm volatile("cp.async.wait_group 1;" ::: "memory"); }

__device__ __forceinline__ void ldm4(uint32_t* r, uint32_t addr) {
    asm volatile("ldmatrix.sync.aligned.m8n8.x4.shared.b16 {%0,%1,%2,%3}, [%4];"
        : "=r"(r[0]), "=r"(r[1]), "=r"(r[2]), "=r"(r[3]) : "r"(addr));
}
__device__ __forceinline__ void mma16(float* d, const uint32_t* a, uint32_t b0, uint32_t b1) {
    asm volatile(
        "mma.sync.aligned.m16n8k16.row.col.f32.f16.f16.f32 "
        "{%0,%1,%2,%3}, {%4,%5,%6,%7}, {%8,%9}, {%0,%1,%2,%3};"
        : "+f"(d[0]), "+f"(d[1]), "+f"(d[2]), "+f"(d[3])
        : "r"(a[0]), "r"(a[1]), "r"(a[2]), "r"(a[3]), "r"(b0), "r"(b1));
}

// ---------------------------------------------------------------------------
// MODE 0: batched fp32 out:  C = alpha * A[M,K] x B[N,K]^T, strides sA/sB/sC.
// MODE 1: fused projections: z=0: Qh = xh Wq + bq
//                            z=1: Kh = ch Wk + bk
//                            z=2: Vt = (ch Wv + bv)^T per batch (half out)
// ---------------------------------------------------------------------------
template <int MODE>
__global__ __launch_bounds__(128, 2)
void gemm_f16(const __half* __restrict__ A0, const __half* __restrict__ A1,
              const __half* __restrict__ Bg,
              const float* __restrict__ b0p, const float* __restrict__ b1p,
              const float* __restrict__ b2p,
              float* __restrict__ Cf,
              __half* __restrict__ O0, __half* __restrict__ O1, __half* __restrict__ O2,
              int M, int N, int K,
              long long sA, long long sB, long long sC, float alpha)
{
    extern __shared__ char smem[];
    const uint32_t sbase = smem_u32(smem);

    const int tid  = threadIdx.x;       // 0..127
    const int wid  = tid >> 5;          // 0..3
    const int lane = tid & 31;
    const int r    = lane >> 2;
    const int cq   = lane & 3;
    const int z    = blockIdx.z;

    const int mBase = (wid >> 1) * 64;
    const int nBase = (wid & 1) * 64;
    const int rowBase = blockIdx.y * BM;
    const int colBase = blockIdx.x * BN;

    const __half* A;
    const __half* B;
    const float*  bias = nullptr;
    if (MODE == 1) {
        A    = (z == 0) ? A0 : A1;
        B    = Bg + (uint32_t)z * (1u << 20);
        bias = (z == 0) ? b0p : (z == 1) ? b1p : b2p;
    } else {
        A = A0 + (long long)z * sA;
        B = Bg + (long long)z * sB;
    }
    A += (long long)rowBase * K;
    B += (long long)colBase * K;

    const int nC = K / BK;

    // 2048 cp16 per stage (A 1024 + B 1024), 128 threads -> 16 each
    auto issue = [&](int cIdx) {
        const long long k0 = (long long)cIdx * BK;
        const uint32_t st = sbase + (uint32_t)((cIdx % NSTAGE) * STAGE_BYTES);
#pragma unroll
        for (int i = 0; i < 16; i++) {
            const int g = tid + i * 128;
            if (g < 1024) {                             // A: 128 rows x 8 chunks
                const int row = g >> 3, cc = g & 7;
                cp16(st + row * RSB + cc * 16, A + (long long)row * K + k0 + cc * 8);
            } else {                                    // B: 128 rows x 8 chunks
                const int h = g - 1024;
                const int row = h >> 3, cc = h & 7;
                cp16(st + B_OFF + row * RSB + cc * 16, B + (long long)row * K + k0 + cc * 8);
            }
        }
        cp_commit();
    };

    const uint32_t aOffB = (uint32_t)((mBase + (lane & 15)) * RSB + ((lane & 16) ? 16 : 0));
    const uint32_t bOffB = (uint32_t)((nBase + (lane & 7) + ((lane & 16) ? 8 : 0)) * RSB
                                      + ((lane & 8) ? 16 : 0));

    float acc[4][8][4];
#pragma unroll
    for (int mi = 0; mi < 4; mi++)
#pragma unroll
        for (int nj = 0; nj < 8; nj++)
#pragma unroll
            for (int q = 0; q < 4; q++) acc[mi][nj][q] = 0.0f;

    uint32_t fa[2][4][4], fb[2][4][4];

    issue(0); issue(1);

    for (int c = 0; c < nC; c++) {
        cp_wait1();
        __syncthreads();
        if (c + 2 < nC) issue(c + 2); else cp_commit();

        const uint32_t st = sbase + (uint32_t)((c % NSTAGE) * STAGE_BYTES);

        // prime sub 0 fragments
#pragma unroll
        for (int mi = 0; mi < 4; mi++)
            ldm4(fa[0][mi], st + aOffB + mi * (16 * RSB));
#pragma unroll
        for (int p = 0; p < 4; p++)
            ldm4(fb[0][p], st + B_OFF + bOffB + p * (16 * RSB));

#pragma unroll
        for (int sub = 0; sub < 4; sub++) {
            const int cur = sub & 1, nxt = cur ^ 1;
            if (sub < 3) {      // prefetch next sub's fragments under current MMAs
#pragma unroll
                for (int mi = 0; mi < 4; mi++)
                    ldm4(fa[nxt][mi], st + aOffB + mi * (16 * RSB) + (sub + 1) * 32);
#pragma unroll
                for (int p = 0; p < 4; p++)
                    ldm4(fb[nxt][p], st + B_OFF + bOffB + p * (16 * RSB) + (sub + 1) * 32);
            }
#pragma unroll
            for (int nj = 0; nj < 8; nj++) {
                const uint32_t bb0 = fb[cur][nj >> 1][(nj & 1) * 2];
                const uint32_t bb1 = fb[cur][nj >> 1][(nj & 1) * 2 + 1];
#pragma unroll
                for (int mi = 0; mi < 4; mi++) mma16(acc[mi][nj], fa[cur][mi], bb0, bb1);
            }
        }
    }
    __syncthreads();

    // ---- epilogue ----
    if (MODE == 0) {
        float* C = Cf + (long long)z * sC;
#pragma unroll
        for (int nj = 0; nj < 8; nj++) {
            const int n0 = colBase + nBase + nj * 8 + 2 * cq;
#pragma unroll
            for (int mi = 0; mi < 4; mi++) {
                const int m0 = rowBase + mBase + mi * 16 + r;
                const float* d = acc[mi][nj];
                *reinterpret_cast<float2*>(&C[(long long)m0 * N + n0]) =
                    make_float2(d[0] * alpha, d[1] * alpha);
                *reinterpret_cast<float2*>(&C[(long long)(m0 + 8) * N + n0]) =
                    make_float2(d[2] * alpha, d[3] * alpha);
            }
        }
    } else {
#pragma unroll
        for (int nj = 0; nj < 8; nj++) {
            const int n0 = colBase + nBase + nj * 8 + 2 * cq;
            const float2 bv = *reinterpret_cast<const float2*>(&bias[n0]);
#pragma unroll
            for (int mi = 0; mi < 4; mi++) {
                const int m0 = rowBase + mBase + mi * 16 + r;
                const float* d = acc[mi][nj];
                const float v0 = d[0] + bv.x, v1 = d[1] + bv.y;
                const float v2 = d[2] + bv.x, v3 = d[3] + bv.y;
                if (z < 2) {
                    __half* O = z ? O1 : O0;
                    *reinterpret_cast<__half2*>(&O[(long long)m0 * 1024 + n0]) =
                        __floats2half2_rn(v0, v1);
                    *reinterpret_cast<__half2*>(&O[(long long)(m0 + 8) * 1024 + n0]) =
                        __floats2half2_rn(v2, v3);
                } else {
                    // V^T: m0 = b*2048 + s, n0 = d  ->  O2[b][d][s]
                    const int bb = m0 >> 11, s = m0 & 2047;
                    __half* O = O2 + (long long)bb * (1024u * 2048u);
                    O[(long long)(n0 + 0) * 2048 + s]     = __float2half_rn(v0);
                    O[(long long)(n0 + 1) * 2048 + s]     = __float2half_rn(v1);
                    O[(long long)(n0 + 0) * 2048 + s + 8] = __float2half_rn(v2);
                    O[(long long)(n0 + 1) * 2048 + s + 8] = __float2half_rn(v3);
                }
            }
        }
    }
}

// ---------------- fp32 -> fp16 convert (x and context fused) ----------------
__global__ __launch_bounds__(256)
void conv_half2(const float* __restrict__ s0, __half* __restrict__ d0,
                const float* __restrict__ s1, __half* __restrict__ d1)
{
    const bool second = blockIdx.x >= 8192;
    const float* src = second ? s1 : s0;
    __half* dst      = second ? d1 : d0;
    const int i = (second ? blockIdx.x - 8192 : blockIdx.x) * 256 + threadIdx.x;
    const float4 v = reinterpret_cast<const float4*>(src)[i];
    reinterpret_cast<__half2*>(dst)[i * 2 + 0] = __floats2half2_rn(v.x, v.y);
    reinterpret_cast<__half2*>(dst)[i * 2 + 1] = __floats2half2_rn(v.z, v.w);
}

// ---------------- transpose 1024x1024 -> fp16, z = weight index ----------------
__global__ __launch_bounds__(256)
void transpose_conv3(const float* __restrict__ w0, const float* __restrict__ w1,
                     const float* __restrict__ w2, __half* __restrict__ t)
{
    __shared__ float ts[32][33];
    const int z = blockIdx.z;
    const float* in = (z == 0) ? w0 : (z == 1) ? w1 : w2;
    __half* tz = t + ((uint32_t)z << 20);
    const int bx = blockIdx.x * 32, by = blockIdx.y * 32;
    const int txl = threadIdx.x, tyl = threadIdx.y;
#pragma unroll
    for (int rr = tyl; rr < 32; rr += 8)
        ts[rr][txl] = in[(long long)(by + rr) * 1024 + bx + txl];
    __syncthreads();
#pragma unroll
    for (int rr = tyl; rr < 32; rr += 8)
        tz[(long long)(bx + rr) * 1024 + by + txl] = __float2half_rn(ts[txl][rr]);
}

// ---------------- softmax: fp32 S row -> fp16 P row ----------------
__global__ __launch_bounds__(256)
void softmax_h(const float* __restrict__ S, __half* __restrict__ Ph)
{
    const float* p = S + (long long)blockIdx.x * 2048;
    const int tid  = threadIdx.x;
    const int wid  = tid >> 5;
    const int lane = tid & 31;
    __shared__ float red[8];

    float4 v0 = reinterpret_cast<const float4*>(p)[tid];
    float4 v1 = reinterpret_cast<const float4*>(p)[tid + 256];

    float m = fmaxf(fmaxf(fmaxf(v0.x, v0.y), fmaxf(v0.z, v0.w)),
                    fmaxf(fmaxf(v1.x, v1.y), fmaxf(v1.z, v1.w)));
#pragma unroll
    for (int o = 16; o; o >>= 1) m = fmaxf(m, __shfl_xor_sync(~0u, m, o));
    if (lane == 0) red[wid] = m;
    __syncthreads();
    m = fmaxf(fmaxf(fmaxf(red[0], red[1]), fmaxf(red[2], red[3])),
              fmaxf(fmaxf(red[4], red[5]), fmaxf(red[6], red[7])));
    __syncthreads();

    v0.x = __expf(v0.x - m); v0.y = __expf(v0.y - m);
    v0.z = __expf(v0.z - m); v0.w = __expf(v0.w - m);
    v1.x = __expf(v1.x - m); v1.y = __expf(v1.y - m);
    v1.z = __expf(v1.z - m); v1.w = __expf(v1.w - m);

    float s = (v0.x + v0.y) + (v0.z + v0.w) + (v1.x + v1.y) + (v1.z + v1.w);
#pragma unroll
    for (int o = 16; o; o >>= 1) s += __shfl_xor_sync(~0u, s, o);
    if (lane == 0) red[wid] = s;
    __syncthreads();
    s = (red[0] + red[1]) + (red[2] + red[3]) + (red[4] + red[5]) + (red[6] + red[7]);
    const float inv = 1.0f / s;

    __half2* PH = reinterpret_cast<__half2*>(Ph + (long long)blockIdx.x * 2048);
    PH[tid * 2 + 0]       = __floats2half2_rn(v0.x * inv, v0.y * inv);
    PH[tid * 2 + 1]       = __floats2half2_rn(v0.z * inv, v0.w * inv);
    PH[512 + tid * 2 + 0] = __floats2half2_rn(v1.x * inv, v1.y * inv);
    PH[512 + tid * 2 + 1] = __floats2half2_rn(v1.z * inv, v1.w * inv);
}

// ---------------------------------------------------------------------------
extern "C" void kernel_launch(void* const* d_in, const int* in_sizes, int n_in,
                              void* d_out, int out_size)
{
    (void)in_sizes; (void)n_in; (void)out_size;
    const float* x       = (const float*)d_in[0];
    const float* context = (const float*)d_in[1];
    const float* Wq      = (const float*)d_in[2];
    const float* bq      = (const float*)d_in[3];
    const float* Wk      = (const float*)d_in[4];
    const float* bk      = (const float*)d_in[5];
    const float* Wv      = (const float*)d_in[6];
    const float* bv      = (const float*)d_in[7];
    float* out = (float*)d_out;

    __half *xh, *ch, *Wt, *Qh, *Kh, *Vt, *Ph;
    float* S;
    cudaGetSymbolAddress((void**)&xh, g_xh);
    cudaGetSymbolAddress((void**)&ch, g_ch);
    cudaGetSymbolAddress((void**)&Wt, g_Wt);
    cudaGetSymbolAddress((void**)&Qh, g_Qh);
    cudaGetSymbolAddress((void**)&Kh, g_Kh);
    cudaGetSymbolAddress((void**)&Vt, g_Vt);
    cudaGetSymbolAddress((void**)&Ph, g_Ph);
    cudaGetSymbolAddress((void**)&S,  g_S);

    cudaFuncSetAttribute(gemm_f16<0>, cudaFuncAttributeMaxDynamicSharedMemorySize, SMEM_BYTES);
    cudaFuncSetAttribute(gemm_f16<1>, cudaFuncAttributeMaxDynamicSharedMemorySize, SMEM_BYTES);

    const float scale = 0.03125f;  // 1/sqrt(1024)

    // prep
    conv_half2<<<16384, 256>>>(x, xh, context, ch);
    transpose_conv3<<<dim3(32, 32, 3), dim3(32, 8)>>>(Wq, Wk, Wv, Wt);

    // fused projections: grid.z = {Q, K, V^T}
    gemm_f16<1><<<dim3(8, 64, 3), 128, SMEM_BYTES>>>(
        xh, ch, Wt, bq, bk, bv, nullptr, Qh, Kh, Vt,
        8192, 1024, 1024, 0, 0, 0, 1.0f);

    // S = scale * Q K^T per batch
    gemm_f16<0><<<dim3(16, 16, 4), 128, SMEM_BYTES>>>(
        Qh, nullptr, Kh, nullptr, nullptr, nullptr, S, nullptr, nullptr, nullptr,
        2048, 2048, 1024, 2048LL * 1024, 2048LL * 1024, 2048LL * 2048, scale);

    softmax_h<<<4 * 2048, 256>>>(S, Ph);

    // out = P V per batch (B = V^T, K-contiguous over SKV)
    gemm_f16<0><<<dim3(8, 16, 4), 128, SMEM_BYTES>>>(
        Ph, nullptr, Vt, nullptr, nullptr, nullptr, out, nullptr, nullptr, nullptr,
        2048, 1024, 2048, 2048LL * 2048, 1024LL * 2048, 2048LL * 1024, 1.0f);
}

// round 13
// speedup vs baseline: 7.2648x; 1.0364x over previous
#include <cuda_runtime.h>
#include <cuda_fp16.h>
#include <cstdint>

// ---------------------------------------------------------------------------
// Cross-attention B=4, SQ=SKV=2048, D=1024, fp32 in/out.
// Single-pass fp16 HMMA (fp32 accumulate). CTA 128x128, 256 threads,
// 8 warps of 32x64, BK=64, 3-stage cp.async, 2 CTAs/SM -> 4 warps/SMSP.
// ---------------------------------------------------------------------------

__device__ __half g_xh [8192u * 1024u];
__device__ __half g_ch [8192u * 1024u];
__device__ __half g_Wt [3u * 1024u * 1024u];    // Wq^T, Wk^T, Wv^T (fp16)
__device__ __half g_Qh [8192u * 1024u];
__device__ __half g_Kh [8192u * 1024u];
__device__ __half g_Vt [4u * 1024u * 2048u];    // V^T per batch [D, SKV]
__device__ __half g_Ph [4u * 2048u * 2048u];
__device__ float  g_S  [4u * 2048u * 2048u];

#define BM 128
#define BN 128
#define BK 64
#define RSB 144                 // smem row stride bytes (128B data + 16B pad)
#define A_BYTES (128 * RSB)     // 18432
#define B_OFF   A_BYTES
#define STAGE_BYTES (2 * A_BYTES)           // 36864
#define NSTAGE 3
#define SMEM_BYTES (NSTAGE * STAGE_BYTES)   // 110592

__device__ __forceinline__ uint32_t smem_u32(const void* p) {
    uint32_t a;
    asm("{ .reg .u64 t; cvta.to.shared.u64 t, %1; cvt.u32.u64 %0, t; }" : "=r"(a) : "l"(p));
    return a;
}
__device__ __forceinline__ void cp16(uint32_t s, const void* g) {
    asm volatile("cp.async.cg.shared.global [%0], [%1], 16;" :: "r"(s), "l"(g) : "memory");
}
__device__ __forceinline__ void cp_commit() { asm volatile("cp.async.commit_group;" ::: "memory"); }
__device__ __forceinline__ void cp_wait1()  { asm volatile("cp.async.wait_group 1;" ::: "memory"); }

__device__ __forceinline__ void ldm4(uint32_t* r, uint32_t addr) {
    asm volatile("ldmatrix.sync.aligned.m8n8.x4.shared.b16 {%0,%1,%2,%3}, [%4];"
        : "=r"(r[0]), "=r"(r[1]), "=r"(r[2]), "=r"(r[3]) : "r"(addr));
}
__device__ __forceinline__ void mma16(float* d, const uint32_t* a, uint32_t b0, uint32_t b1) {
    asm volatile(
        "mma.sync.aligned.m16n8k16.row.col.f32.f16.f16.f32 "
        "{%0,%1,%2,%3}, {%4,%5,%6,%7}, {%8,%9}, {%0,%1,%2,%3};"
        : "+f"(d[0]), "+f"(d[1]), "+f"(d[2]), "+f"(d[3])
        : "r"(a[0]), "r"(a[1]), "r"(a[2]), "r"(a[3]), "r"(b0), "r"(b1));
}

// ---------------------------------------------------------------------------
// MODE 0: batched fp32 out:  C = alpha * A[M,K] x B[N,K]^T, strides sA/sB/sC.
// MODE 1: fused projections: z=0: Qh = xh Wq + bq
//                            z=1: Kh = ch Wk + bk
//                            z=2: Vt = (ch Wv + bv)^T per batch (half out)
// ---------------------------------------------------------------------------
template <int MODE>
__global__ __launch_bounds__(256, 2)
void gemm_f16(const __half* __restrict__ A0, const __half* __restrict__ A1,
              const __half* __restrict__ Bg,
              const float* __restrict__ b0p, const float* __restrict__ b1p,
              const float* __restrict__ b2p,
              float* __restrict__ Cf,
              __half* __restrict__ O0, __half* __restrict__ O1, __half* __restrict__ O2,
              int M, int N, int K,
              long long sA, long long sB, long long sC, float alpha)
{
    extern __shared__ char smem[];
    const uint32_t sbase = smem_u32(smem);

    const int tid  = threadIdx.x;       // 0..255
    const int wid  = tid >> 5;          // 0..7
    const int lane = tid & 31;
    const int r    = lane >> 2;
    const int cq   = lane & 3;
    const int z    = blockIdx.z;

    const int mBase = (wid & 3) * 32;   // 4 M-groups of 32 rows
    const int nBase = (wid >> 2) * 64;  // 2 N-groups of 64 cols
    const int rowBase = blockIdx.y * BM;
    const int colBase = blockIdx.x * BN;

    const __half* A;
    const __half* B;
    const float*  bias = nullptr;
    if (MODE == 1) {
        A    = (z == 0) ? A0 : A1;
        B    = Bg + (uint32_t)z * (1u << 20);
        bias = (z == 0) ? b0p : (z == 1) ? b1p : b2p;
    } else {
        A = A0 + (long long)z * sA;
        B = Bg + (long long)z * sB;
    }
    A += (long long)rowBase * K;
    B += (long long)colBase * K;

    const int nC = K / BK;

    // 2048 cp16 per stage (A 1024 + B 1024), 256 threads -> 8 each
    auto issue = [&](int cIdx) {
        const long long k0 = (long long)cIdx * BK;
        const uint32_t st = sbase + (uint32_t)((cIdx % NSTAGE) * STAGE_BYTES);
#pragma unroll
        for (int i = 0; i < 8; i++) {
            const int g = tid + i * 256;
            if (g < 1024) {                             // A: 128 rows x 8 chunks
                const int row = g >> 3, cc = g & 7;
                cp16(st + row * RSB + cc * 16, A + (long long)row * K + k0 + cc * 8);
            } else {                                    // B: 128 rows x 8 chunks
                const int h = g - 1024;
                const int row = h >> 3, cc = h & 7;
                cp16(st + B_OFF + row * RSB + cc * 16, B + (long long)row * K + k0 + cc * 8);
            }
        }
        cp_commit();
    };

    const uint32_t aOffB = (uint32_t)((mBase + (lane & 15)) * RSB + ((lane & 16) ? 16 : 0));
    const uint32_t bOffB = (uint32_t)((nBase + (lane & 7) + ((lane & 16) ? 8 : 0)) * RSB
                                      + ((lane & 8) ? 16 : 0));

    float acc[2][8][4];
#pragma unroll
    for (int mi = 0; mi < 2; mi++)
#pragma unroll
        for (int nj = 0; nj < 8; nj++)
#pragma unroll
            for (int q = 0; q < 4; q++) acc[mi][nj][q] = 0.0f;

    issue(0); issue(1);

    for (int c = 0; c < nC; c++) {
        cp_wait1();
        __syncthreads();
        if (c + 2 < nC) issue(c + 2); else cp_commit();

        const uint32_t st = sbase + (uint32_t)((c % NSTAGE) * STAGE_BYTES);

#pragma unroll
        for (int sub = 0; sub < 4; sub++) {
            uint32_t fa[2][4], fb[4][4];
#pragma unroll
            for (int mi = 0; mi < 2; mi++)
                ldm4(fa[mi], st + aOffB + mi * (16 * RSB) + sub * 32);
#pragma unroll
            for (int p = 0; p < 4; p++)
                ldm4(fb[p], st + B_OFF + bOffB + p * (16 * RSB) + sub * 32);
#pragma unroll
            for (int nj = 0; nj < 8; nj++) {
                const uint32_t bb0 = fb[nj >> 1][(nj & 1) * 2];
                const uint32_t bb1 = fb[nj >> 1][(nj & 1) * 2 + 1];
#pragma unroll
                for (int mi = 0; mi < 2; mi++) mma16(acc[mi][nj], fa[mi], bb0, bb1);
            }
        }
    }
    __syncthreads();

    // ---- epilogue ----
    if (MODE == 0) {
        float* C = Cf + (long long)z * sC;
#pragma unroll
        for (int nj = 0; nj < 8; nj++) {
            const int n0 = colBase + nBase + nj * 8 + 2 * cq;
#pragma unroll
            for (int mi = 0; mi < 2; mi++) {
                const int m0 = rowBase + mBase + mi * 16 + r;
                const float* d = acc[mi][nj];
                *reinterpret_cast<float2*>(&C[(long long)m0 * N + n0]) =
                    make_float2(d[0] * alpha, d[1] * alpha);
                *reinterpret_cast<float2*>(&C[(long long)(m0 + 8) * N + n0]) =
                    make_float2(d[2] * alpha, d[3] * alpha);
            }
        }
    } else {
#pragma unroll
        for (int nj = 0; nj < 8; nj++) {
            const int n0 = colBase + nBase + nj * 8 + 2 * cq;
            const float2 bv = *reinterpret_cast<const float2*>(&bias[n0]);
#pragma unroll
            for (int mi = 0; mi < 2; mi++) {
                const int m0 = rowBase + mBase + mi * 16 + r;
                const float* d = acc[mi][nj];
                const float v0 = d[0] + bv.x, v1 = d[1] + bv.y;
                const float v2 = d[2] + bv.x, v3 = d[3] + bv.y;
                if (z < 2) {
                    __half* O = z ? O1 : O0;
                    *reinterpret_cast<__half2*>(&O[(long long)m0 * 1024 + n0]) =
                        __floats2half2_rn(v0, v1);
                    *reinterpret_cast<__half2*>(&O[(long long)(m0 + 8) * 1024 + n0]) =
                        __floats2half2_rn(v2, v3);
                } else {
                    // V^T: m0 = b*2048 + s, n0 = d  ->  O2[b][d][s]
                    const int bb = m0 >> 11, s = m0 & 2047;
                    __half* O = O2 + (long long)bb * (1024u * 2048u);
                    O[(long long)(n0 + 0) * 2048 + s]     = __float2half_rn(v0);
                    O[(long long)(n0 + 1) * 2048 + s]     = __float2half_rn(v1);
                    O[(long long)(n0 + 0) * 2048 + s + 8] = __float2half_rn(v2);
                    O[(long long)(n0 + 1) * 2048 + s + 8] = __float2half_rn(v3);
                }
            }
        }
    }
}

// ---------------- fp32 -> fp16 convert (x and context fused) ----------------
__global__ __launch_bounds__(256)
void conv_half2(const float* __restrict__ s0, __half* __restrict__ d0,
                const float* __restrict__ s1, __half* __restrict__ d1)
{
    const bool second = blockIdx.x >= 8192;
    const float* src = second ? s1 : s0;
    __half* dst      = second ? d1 : d0;
    const int i = (second ? blockIdx.x - 8192 : blockIdx.x) * 256 + threadIdx.x;
    const float4 v = reinterpret_cast<const float4*>(src)[i];
    reinterpret_cast<__half2*>(dst)[i * 2 + 0] = __floats2half2_rn(v.x, v.y);
    reinterpret_cast<__half2*>(dst)[i * 2 + 1] = __floats2half2_rn(v.z, v.w);
}

// ---------------- transpose 1024x1024 -> fp16, z = weight index ----------------
__global__ __launch_bounds__(256)
void transpose_conv3(const float* __restrict__ w0, const float* __restrict__ w1,
                     const float* __restrict__ w2, __half* __restrict__ t)
{
    __shared__ float ts[32][33];
    const int z = blockIdx.z;
    const float* in = (z == 0) ? w0 : (z == 1) ? w1 : w2;
    __half* tz = t + ((uint32_t)z << 20);
    const int bx = blockIdx.x * 32, by = blockIdx.y * 32;
    const int txl = threadIdx.x, tyl = threadIdx.y;
#pragma unroll
    for (int rr = tyl; rr < 32; rr += 8)
        ts[rr][txl] = in[(long long)(by + rr) * 1024 + bx + txl];
    __syncthreads();
#pragma unroll
    for (int rr = tyl; rr < 32; rr += 8)
        tz[(long long)(bx + rr) * 1024 + by + txl] = __float2half_rn(ts[txl][rr]);
}

// ---------------- softmax: fp32 S row -> fp16 P row ----------------
__global__ __launch_bounds__(256)
void softmax_h(const float* __restrict__ S, __half* __restrict__ Ph)
{
    const float* p = S + (long long)blockIdx.x * 2048;
    const int tid  = threadIdx.x;
    const int wid  = tid >> 5;
    const int lane = tid & 31;
    __shared__ float red[8];

    float4 v0 = reinterpret_cast<const float4*>(p)[tid];
    float4 v1 = reinterpret_cast<const float4*>(p)[tid + 256];

    float m = fmaxf(fmaxf(fmaxf(v0.x, v0.y), fmaxf(v0.z, v0.w)),
                    fmaxf(fmaxf(v1.x, v1.y), fmaxf(v1.z, v1.w)));
#pragma unroll
    for (int o = 16; o; o >>= 1) m = fmaxf(m, __shfl_xor_sync(~0u, m, o));
    if (lane == 0) red[wid] = m;
    __syncthreads();
    m = fmaxf(fmaxf(fmaxf(red[0], red[1]), fmaxf(red[2], red[3])),
              fmaxf(fmaxf(red[4], red[5]), fmaxf(red[6], red[7])));
    __syncthreads();

    v0.x = __expf(v0.x - m); v0.y = __expf(v0.y - m);
    v0.z = __expf(v0.z - m); v0.w = __expf(v0.w - m);
    v1.x = __expf(v1.x - m); v1.y = __expf(v1.y - m);
    v1.z = __expf(v1.z - m); v1.w = __expf(v1.w - m);

    float s = (v0.x + v0.y) + (v0.z + v0.w) + (v1.x + v1.y) + (v1.z + v1.w);
#pragma unroll
    for (int o = 16; o; o >>= 1) s += __shfl_xor_sync(~0u, s, o);
    if (lane == 0) red[wid] = s;
    __syncthreads();
    s = (red[0] + red[1]) + (red[2] + red[3]) + (red[4] + red[5]) + (red[6] + red[7]);
    const float inv = 1.0f / s;

    __half2* PH = reinterpret_cast<__half2*>(Ph + (long long)blockIdx.x * 2048);
    PH[tid * 2 + 0]       = __floats2half2_rn(v0.x * inv, v0.y * inv);
    PH[tid * 2 + 1]       = __floats2half2_rn(v0.z * inv, v0.w * inv);
    PH[512 + tid * 2 + 0] = __floats2half2_rn(v1.x * inv, v1.y * inv);
    PH[512 + tid * 2 + 1] = __floats2half2_rn(v1.z * inv, v1.w * inv);
}

// ---------------------------------------------------------------------------
extern "C" void kernel_launch(void* const* d_in, const int* in_sizes, int n_in,
                              void* d_out, int out_size)
{
    (void)in_sizes; (void)n_in; (void)out_size;
    const float* x       = (const float*)d_in[0];
    const float* context = (const float*)d_in[1];
    const float* Wq      = (const float*)d_in[2];
    const float* bq      = (const float*)d_in[3];
    const float* Wk      = (const float*)d_in[4];
    const float* bk      = (const float*)d_in[5];
    const float* Wv      = (const float*)d_in[6];
    const float* bv      = (const float*)d_in[7];
    float* out = (float*)d_out;

    __half *xh, *ch, *Wt, *Qh, *Kh, *Vt, *Ph;
    float* S;
    cudaGetSymbolAddress((void**)&xh, g_xh);
    cudaGetSymbolAddress((void**)&ch, g_ch);
    cudaGetSymbolAddress((void**)&Wt, g_Wt);
    cudaGetSymbolAddress((void**)&Qh, g_Qh);
    cudaGetSymbolAddress((void**)&Kh, g_Kh);
    cudaGetSymbolAddress((void**)&Vt, g_Vt);
    cudaGetSymbolAddress((void**)&Ph, g_Ph);
    cudaGetSymbolAddress((void**)&S,  g_S);

    cudaFuncSetAttribute(gemm_f16<0>, cudaFuncAttributeMaxDynamicSharedMemorySize, SMEM_BYTES);
    cudaFuncSetAttribute(gemm_f16<1>, cudaFuncAttributeMaxDynamicSharedMemorySize, SMEM_BYTES);

    const float scale = 0.03125f;  // 1/sqrt(1024)

    // prep
    conv_half2<<<16384, 256>>>(x, xh, context, ch);
    transpose_conv3<<<dim3(32, 32, 3), dim3(32, 8)>>>(Wq, Wk, Wv, Wt);

    // fused projections: grid.z = {Q, K, V^T}
    gemm_f16<1><<<dim3(8, 64, 3), 256, SMEM_BYTES>>>(
        xh, ch, Wt, bq, bk, bv, nullptr, Qh, Kh, Vt,
        8192, 1024, 1024, 0, 0, 0, 1.0f);

    // S = scale * Q K^T per batch
    gemm_f16<0><<<dim3(16, 16, 4), 256, SMEM_BYTES>>>(
        Qh, nullptr, Kh, nullptr, nullptr, nullptr, S, nullptr, nullptr, nullptr,
        2048, 2048, 1024, 2048LL * 1024, 2048LL * 1024, 2048LL * 2048, scale);

    softmax_h<<<4 * 2048, 256>>>(S, Ph);

    // out = P V per batch (B = V^T, K-contiguous over SKV)
    gemm_f16<0><<<dim3(8, 16, 4), 256, SMEM_BYTES>>>(
        Ph, nullptr, Vt, nullptr, nullptr, nullptr, out, nullptr, nullptr, nullptr,
        2048, 1024, 2048, 2048LL * 2048, 1024LL * 2048, 2048LL * 1024, 1.0f);
}